// round 12
// baseline (speedup 1.0000x reference)
#include <cuda_runtime.h>
#include <math.h>

// ---------------- problem constants ----------------
#define NIN    20000          // B_AG * N_PTS
#define CAP0   540000         // 27 * NIN
#define CAP1   352000         // B_AG * Z1*Y1*X1
#define ZD     10
#define YD     200
#define XD     704
#define Z1D    5
#define Y1D    100
#define X1D    352
#define HW     (YD*XD)        // 140800
#define HW1    (Y1D*X1D)      // 35200
#define EPSB   1e-5f

// ---------------- static device scratch ----------------
__device__ float g_fin [NIN * 32];
__device__ float g_f0a [(CAP0 + 1) * 32];
__device__ float g_f0b [(CAP0 + 1) * 32];
__device__ float g_f1a [(CAP1 + 1) * 64];
__device__ float g_f1b [(CAP1 + 1) * 64];
__device__ float g_d0  [2 * HW  * 320];              // [b*HW+p][z*32+c]
__device__ float g_d1  [2 * HW1 * 320];              // [b*HW1+p][z*64+c]
__device__ float g_bev0[2 * 64 * HW];                // [b*64+o][p]
__device__ float g_bev1[2 * 64 * HW];
__device__ float g_w0p [320 * 64];
__device__ float g_w1p [320 * 256];
__device__ int   g_cnt [108];

// ---------------- packed f32x2 helpers ----------------
__device__ __forceinline__ void fma2(unsigned long long& acc, unsigned long long a,
                                     unsigned long long b) {
    asm("fma.rn.f32x2 %0, %1, %2, %0;" : "+l"(acc) : "l"(a), "l"(b));
}
__device__ __forceinline__ void lds_2x64(unsigned long long& a, unsigned long long& b,
                                         unsigned addr) {
    asm volatile("ld.shared.v2.b64 {%0, %1}, [%2];" : "=l"(a), "=l"(b) : "r"(addr));
}
__device__ __forceinline__ unsigned long long pack2(float x, float y) {
    unsigned long long r;
    asm("mov.b64 %0, {%1, %2};" : "=l"(r) : "f"(x), "f"(y));
    return r;
}
__device__ __forceinline__ float hsum2(unsigned long long a) {
    float x, y;
    asm("mov.b64 {%0, %1}, %2;" : "=f"(x), "=f"(y) : "l"(a));
    return x + y;
}
__device__ __forceinline__ void redv2(float* p, float a, float b) {
    asm volatile("red.global.add.v2.f32 [%0], {%1, %2};" :: "l"(p), "f"(a), "f"(b)
                 : "memory");
}

// ---------------- rulebook pair counts ----------------
__global__ void k_counts(const int* __restrict__ s0, const int* __restrict__ sa,
                         const int* __restrict__ s1, const int* __restrict__ sb) {
    int t = blockIdx.x * blockDim.x + threadIdx.x;
    if (t >= 108) return;
    int rb = t / 27, k = t % 27;
    const int* S; int pc, cap;
    if      (rb == 0) { S = s0; pc = NIN;  cap = CAP0; }
    else if (rb == 1) { S = sa; pc = CAP0; cap = CAP0; }
    else if (rb == 2) { S = s1; pc = CAP0; cap = CAP1; }
    else              { S = sb; pc = CAP1; cap = CAP1; }
    const int* row = S + (size_t)k * pc;
    int lo = 0, hi = pc;
    while (lo < hi) {
        int mid = (lo + hi) >> 1;
        if (row[mid] == cap) hi = mid; else lo = mid + 1;
    }
    g_cnt[t] = lo;
}

// ---------------- input GEMM ----------------
__global__ void k_gemm_in(const float* __restrict__ sp, const float* __restrict__ w,
                          float* __restrict__ out) {
    int t = blockIdx.x * blockDim.x + threadIdx.x;
    if (t >= NIN * 32) return;
    int i = t >> 5, j = t & 31;
    const float* r = sp + i * 64;
    float acc = 0.f;
#pragma unroll
    for (int c = 0; c < 64; c++) acc += r[c] * w[c * 32 + j];
    out[t] = acc;
}

// ---------------- spconv CIN=32 COUT=32: 2 pairs/warp (halves), batch-2 (R8) ---------
template<bool BN, int NB>
__global__ void __launch_bounds__(256) k_spconv32(
    const float* __restrict__ feats, const int* __restrict__ G, const int* __restrict__ S,
    const float* __restrict__ W, const float* __restrict__ bn,
    float* __restrict__ out, int pair_cap, const int* __restrict__ cnt) {
    __shared__ float slot[8][2][2][32];      // [warp][buf][half][row]
    int k = blockIdx.x / NB;
    int lane = threadIdx.x & 31;
    int warp = threadIdx.x >> 5;
    int half = lane >> 4;
    int j = lane & 15;
    const float* Wk = W + (size_t)k * 1024;
    unsigned long long wA[16], wB[16];
#pragma unroll
    for (int i = 0; i < 16; i++) {
        wA[i] = pack2(Wk[(2 * i) * 32 + 2 * j],     Wk[(2 * i + 1) * 32 + 2 * j]);
        wB[i] = pack2(Wk[(2 * i) * 32 + 2 * j + 1], Wk[(2 * i + 1) * 32 + 2 * j + 1]);
    }
    float sc[4] = {1.f,1.f,1.f,1.f}, of[4] = {0.f,0.f,0.f,0.f};
    if (BN && j < 8) {
#pragma unroll
        for (int c = 0; c < 4; c++) {
            int idx = 4 * j + c;
            sc[c] = bn[idx] * rsqrtf(bn[96 + idx] + EPSB);
            of[c] = bn[32 + idx] - bn[64 + idx] * sc[c];
        }
    }
    int n = cnt[k];
    const int* Gk = G + (size_t)k * pair_cap;
    const int* Sk = S + (size_t)k * pair_cap;
    int base = ((blockIdx.x % NB) * 8 + warp) * 2;
    const int stride = NB * 16;
    unsigned sa0 = (unsigned)__cvta_generic_to_shared(&slot[warp][0][half][0]);
    unsigned sa1 = (unsigned)__cvta_generic_to_shared(&slot[warp][1][half][0]);
    for (int pb = base; pb < n; pb += 2 * stride) {
        int p0 = pb + half, p1 = pb + stride + half;
        bool a0 = p0 < n, a1 = p1 < n;
        int g0 = 0, s0 = 0, g1 = 0, s1 = 0;
        if (a0) { g0 = Gk[p0]; s0 = Sk[p0]; }
        if (a1) { g1 = Gk[p1]; s1 = Sk[p1]; }
        float4 f0 = make_float4(0,0,0,0), f1 = make_float4(0,0,0,0);
        if (a0 && j < 8) f0 = *(const float4*)(feats + (size_t)g0 * 32 + 4 * j);
        if (a1 && j < 8) f1 = *(const float4*)(feats + (size_t)g1 * 32 + 4 * j);
        if (j < 8) {
            if (BN) {
                f0.x = fmaxf(f0.x * sc[0] + of[0], 0.f); f0.y = fmaxf(f0.y * sc[1] + of[1], 0.f);
                f0.z = fmaxf(f0.z * sc[2] + of[2], 0.f); f0.w = fmaxf(f0.w * sc[3] + of[3], 0.f);
                f1.x = fmaxf(f1.x * sc[0] + of[0], 0.f); f1.y = fmaxf(f1.y * sc[1] + of[1], 0.f);
                f1.z = fmaxf(f1.z * sc[2] + of[2], 0.f); f1.w = fmaxf(f1.w * sc[3] + of[3], 0.f);
            }
            if (a0) *(float4*)&slot[warp][0][half][4 * j] = f0;
            if (a1) *(float4*)&slot[warp][1][half][4 * j] = f1;
        }
        __syncwarp();
        unsigned long long A = 0ull, B = 0ull;
#pragma unroll
        for (int i = 0; i < 8; i++) {
            unsigned long long va, vb;
            lds_2x64(va, vb, sa0 + i * 16);
            fma2(A, va, wA[2 * i]); fma2(B, va, wB[2 * i]);
            fma2(A, vb, wA[2 * i + 1]); fma2(B, vb, wB[2 * i + 1]);
        }
        if (a0) redv2(out + (size_t)s0 * 32 + 2 * j, hsum2(A), hsum2(B));
        A = 0ull; B = 0ull;
#pragma unroll
        for (int i = 0; i < 8; i++) {
            unsigned long long va, vb;
            lds_2x64(va, vb, sa1 + i * 16);
            fma2(A, va, wA[2 * i]); fma2(B, va, wB[2 * i]);
            fma2(A, vb, wA[2 * i + 1]); fma2(B, vb, wB[2 * i + 1]);
        }
        if (a1) redv2(out + (size_t)s1 * 32 + 2 * j, hsum2(A), hsum2(B));
        __syncwarp();
    }
}

// ---------------- spconv CIN=32 COUT=64: warp/pair, batch-2 (R8) ---------------------
template<bool BN, int NB>
__global__ void __launch_bounds__(256) k_spconv3264(
    const float* __restrict__ feats, const int* __restrict__ G, const int* __restrict__ S,
    const float* __restrict__ W, const float* __restrict__ bn,
    float* __restrict__ out, int pair_cap, const int* __restrict__ cnt) {
    __shared__ float slot[8][2][32];
    int k = blockIdx.x / NB;
    int lane = threadIdx.x & 31;
    int warp = threadIdx.x >> 5;
    const float* Wk = W + (size_t)k * 2048;
    unsigned long long wA[16], wB[16];
#pragma unroll
    for (int i = 0; i < 16; i++) {
        wA[i] = pack2(Wk[(2 * i) * 64 + 2 * lane],     Wk[(2 * i + 1) * 64 + 2 * lane]);
        wB[i] = pack2(Wk[(2 * i) * 64 + 2 * lane + 1], Wk[(2 * i + 1) * 64 + 2 * lane + 1]);
    }
    float sc[4] = {1.f,1.f,1.f,1.f}, of[4] = {0.f,0.f,0.f,0.f};
    if (BN && lane < 8) {
#pragma unroll
        for (int c = 0; c < 4; c++) {
            int idx = 4 * lane + c;
            sc[c] = bn[idx] * rsqrtf(bn[96 + idx] + EPSB);
            of[c] = bn[32 + idx] - bn[64 + idx] * sc[c];
        }
    }
    int n = cnt[k];
    const int* Gk = G + (size_t)k * pair_cap;
    const int* Sk = S + (size_t)k * pair_cap;
    int base = (blockIdx.x % NB) * 8 + warp;
    const int stride = NB * 8;
    unsigned sa0 = (unsigned)__cvta_generic_to_shared(&slot[warp][0][0]);
    unsigned sa1 = (unsigned)__cvta_generic_to_shared(&slot[warp][1][0]);
    for (int p = base; p < n; p += 2 * stride) {
        int p1 = p + stride;
        bool a1 = p1 < n;
        int g0 = Gk[p], s0 = Sk[p], g1 = 0, s1 = 0;
        if (a1) { g1 = Gk[p1]; s1 = Sk[p1]; }
        float4 f0 = make_float4(0,0,0,0), f1 = make_float4(0,0,0,0);
        if (lane < 8) {
            f0 = *(const float4*)(feats + (size_t)g0 * 32 + 4 * lane);
            if (a1) f1 = *(const float4*)(feats + (size_t)g1 * 32 + 4 * lane);
            if (BN) {
                f0.x = fmaxf(f0.x * sc[0] + of[0], 0.f); f0.y = fmaxf(f0.y * sc[1] + of[1], 0.f);
                f0.z = fmaxf(f0.z * sc[2] + of[2], 0.f); f0.w = fmaxf(f0.w * sc[3] + of[3], 0.f);
                f1.x = fmaxf(f1.x * sc[0] + of[0], 0.f); f1.y = fmaxf(f1.y * sc[1] + of[1], 0.f);
                f1.z = fmaxf(f1.z * sc[2] + of[2], 0.f); f1.w = fmaxf(f1.w * sc[3] + of[3], 0.f);
            }
            *(float4*)&slot[warp][0][4 * lane] = f0;
            if (a1) *(float4*)&slot[warp][1][4 * lane] = f1;
        }
        __syncwarp();
        unsigned long long A = 0ull, B = 0ull;
#pragma unroll
        for (int i = 0; i < 8; i++) {
            unsigned long long va, vb;
            lds_2x64(va, vb, sa0 + i * 16);
            fma2(A, va, wA[2 * i]); fma2(B, va, wB[2 * i]);
            fma2(A, vb, wA[2 * i + 1]); fma2(B, vb, wB[2 * i + 1]);
        }
        redv2(out + (size_t)s0 * 64 + 2 * lane, hsum2(A), hsum2(B));
        if (a1) {
            A = 0ull; B = 0ull;
#pragma unroll
            for (int i = 0; i < 8; i++) {
                unsigned long long va, vb;
                lds_2x64(va, vb, sa1 + i * 16);
                fma2(A, va, wA[2 * i]); fma2(B, va, wB[2 * i]);
                fma2(A, vb, wA[2 * i + 1]); fma2(B, vb, wB[2 * i + 1]);
            }
            redv2(out + (size_t)s1 * 64 + 2 * lane, hsum2(A), hsum2(B));
        }
        __syncwarp();
    }
}

// ---------------- spconv CIN=64 COUT=64: K-SPLIT across 2 warps, batch-2 -------------
// Warp pair (slot) handles one rulebook pair; warp kh owns input channels
// [kh*32, kh*32+32). Gathers are partitioned (no duplication); both warps RED
// partial sums to the same 64 outputs. Weight regs: 32 b64 -> doubled occupancy.
template<bool BN, int NB>
__global__ void __launch_bounds__(128) k_spconv64(
    const float* __restrict__ feats, const int* __restrict__ G, const int* __restrict__ S,
    const float* __restrict__ W, const float* __restrict__ bn,
    float* __restrict__ out, int pair_cap, const int* __restrict__ cnt) {
    __shared__ float slot[4][2][32];         // [warp][buf][half feature row]
    int k = blockIdx.x / NB;
    int lane = threadIdx.x & 31;
    int warp = threadIdx.x >> 5;
    int kh = warp & 1;                        // K-half this warp owns
    const float* Wk = W + (size_t)k * 4096 + (size_t)kh * 32 * 64;
    unsigned long long wA[16], wB[16];        // 32 regs
#pragma unroll
    for (int i = 0; i < 16; i++) {
        wA[i] = pack2(Wk[(2 * i) * 64 + 2 * lane],     Wk[(2 * i + 1) * 64 + 2 * lane]);
        wB[i] = pack2(Wk[(2 * i) * 64 + 2 * lane + 1], Wk[(2 * i + 1) * 64 + 2 * lane + 1]);
    }
    // BN constants for the 4 input channels this lane loads (kh*32 + 4*lane.. when lane<8)
    float sc[4] = {1.f,1.f,1.f,1.f}, of[4] = {0.f,0.f,0.f,0.f};
    if (BN && lane < 8) {
#pragma unroll
        for (int c = 0; c < 4; c++) {
            int idx = kh * 32 + 4 * lane + c;
            sc[c] = bn[idx] * rsqrtf(bn[192 + idx] + EPSB);
            of[c] = bn[64 + idx] - bn[128 + idx] * sc[c];
        }
    }
    int n = cnt[k];
    const int* Gk = G + (size_t)k * pair_cap;
    const int* Sk = S + (size_t)k * pair_cap;
    int base = (blockIdx.x % NB) * 2 + (warp >> 1);
    const int stride = NB * 2;
    unsigned sa0 = (unsigned)__cvta_generic_to_shared(&slot[warp][0][0]);
    unsigned sa1 = (unsigned)__cvta_generic_to_shared(&slot[warp][1][0]);
    for (int p = base; p < n; p += 2 * stride) {
        int p1 = p + stride;
        bool a1 = p1 < n;
        int g0 = Gk[p], s0 = Sk[p], g1 = 0, s1 = 0;
        if (a1) { g1 = Gk[p1]; s1 = Sk[p1]; }
        if (lane < 8) {
            float4 f0 = *(const float4*)(feats + (size_t)g0 * 64 + kh * 32 + 4 * lane);
            float4 f1 = make_float4(0,0,0,0);
            if (a1) f1 = *(const float4*)(feats + (size_t)g1 * 64 + kh * 32 + 4 * lane);
            if (BN) {
                f0.x = fmaxf(f0.x * sc[0] + of[0], 0.f); f0.y = fmaxf(f0.y * sc[1] + of[1], 0.f);
                f0.z = fmaxf(f0.z * sc[2] + of[2], 0.f); f0.w = fmaxf(f0.w * sc[3] + of[3], 0.f);
                f1.x = fmaxf(f1.x * sc[0] + of[0], 0.f); f1.y = fmaxf(f1.y * sc[1] + of[1], 0.f);
                f1.z = fmaxf(f1.z * sc[2] + of[2], 0.f); f1.w = fmaxf(f1.w * sc[3] + of[3], 0.f);
            }
            *(float4*)&slot[warp][0][4 * lane] = f0;
            if (a1) *(float4*)&slot[warp][1][4 * lane] = f1;
        }
        __syncwarp();
        unsigned long long A = 0ull, B = 0ull;
#pragma unroll
        for (int i = 0; i < 8; i++) {
            unsigned long long va, vb;
            lds_2x64(va, vb, sa0 + i * 16);
            fma2(A, va, wA[2 * i]); fma2(B, va, wB[2 * i]);
            fma2(A, vb, wA[2 * i + 1]); fma2(B, vb, wB[2 * i + 1]);
        }
        redv2(out + (size_t)s0 * 64 + 2 * lane, hsum2(A), hsum2(B));
        if (a1) {
            A = 0ull; B = 0ull;
#pragma unroll
            for (int i = 0; i < 8; i++) {
                unsigned long long va, vb;
                lds_2x64(va, vb, sa1 + i * 16);
                fma2(A, va, wA[2 * i]); fma2(B, va, wB[2 * i]);
                fma2(A, vb, wA[2 * i + 1]); fma2(B, vb, wB[2 * i + 1]);
            }
            redv2(out + (size_t)s1 * 64 + 2 * lane, hsum2(A), hsum2(B));
        }
        __syncwarp();
    }
}

// ---------------- sparse -> dense scatter with fused BN+ReLU ----------------
__global__ void k_scatter0(const float* __restrict__ f, const int* __restrict__ co,
                           const float* __restrict__ bn, float* __restrict__ d0) {
    int lane = threadIdx.x & 31;
    float sc = bn[lane] * rsqrtf(bn[96 + lane] + EPSB);
    float of = bn[32 + lane] - bn[64 + lane] * sc;
    int warps_total = (gridDim.x * blockDim.x) >> 5;
    for (unsigned w = (blockIdx.x * blockDim.x + threadIdx.x) >> 5; w < CAP0;
         w += warps_total) {
        int z = co[4 * w + 1];
        if ((unsigned)z >= (unsigned)ZD) continue;
        int b = co[4 * w], y = co[4 * w + 2], x = co[4 * w + 3];
        size_t base = ((size_t)(b * HW + y * XD + x)) * 320 + z * 32;
        d0[base + lane] = fmaxf(f[(size_t)w * 32 + lane] * sc + of, 0.f);
    }
}

__global__ void k_scatter1(const float* __restrict__ f, const int* __restrict__ co,
                           const float* __restrict__ bn, float* __restrict__ d1) {
    int lane = threadIdx.x & 31;
    float scA = bn[lane] * rsqrtf(bn[192 + lane] + EPSB);
    float ofA = bn[64 + lane] - bn[128 + lane] * scA;
    float scB = bn[lane + 32] * rsqrtf(bn[192 + lane + 32] + EPSB);
    float ofB = bn[64 + lane + 32] - bn[128 + lane + 32] * scB;
    int warps_total = (gridDim.x * blockDim.x) >> 5;
    for (unsigned w = (blockIdx.x * blockDim.x + threadIdx.x) >> 5; w < CAP1;
         w += warps_total) {
        int z = co[4 * w + 1];
        if ((unsigned)z >= (unsigned)Z1D) continue;
        int b = co[4 * w], y = co[4 * w + 2], x = co[4 * w + 3];
        size_t base = ((size_t)(b * HW1 + y * X1D + x)) * 320 + z * 64;
        d1[base + lane]      = fmaxf(f[(size_t)w * 64 + lane] * scA + ofA, 0.f);
        d1[base + lane + 32] = fmaxf(f[(size_t)w * 64 + lane + 32] * scB + ofB, 0.f);
    }
}

// ---------------- weight permutes ----------------
__global__ void k_permw0(const float* __restrict__ w, float* __restrict__ wp) {
    int t = blockIdx.x * blockDim.x + threadIdx.x;
    if (t >= 320 * 64) return;
    int o = t & 63, kk = t >> 6;
    int z = kk >> 5, c = kk & 31;
    wp[t] = w[(c * 10 + z) * 64 + o];
}
__global__ void k_permw1(const float* __restrict__ w, float* __restrict__ wp) {
    int t = blockIdx.x * blockDim.x + threadIdx.x;
    if (t >= 320 * 256) return;
    int col = t & 255, kk = t >> 8;
    int ij = col >> 6, o = col & 63;
    int z = kk >> 6, c = kk & 63;
    wp[t] = w[((c * 5 + z) * 64 + o) * 4 + ij];
}

// ---------------- tiled GEMM 64x64, K=320 ----------------
__global__ void k_gemm_bev0(const float* __restrict__ A, const float* __restrict__ B,
                            const float* __restrict__ bias, const float* __restrict__ bn,
                            float* __restrict__ bev) {
    __shared__ float As[16][72];
    __shared__ float Bs[16][64];
    int tid = threadIdx.x;
    int tx = tid & 15, ty = tid >> 4;
    int row0 = blockIdx.x * 64;
    float acc[4][4] = {};
    int lr = tid >> 2, lk = (tid & 3) * 4;
    int bk = tid >> 4, bc = (tid & 15) * 4;
    for (int k0 = 0; k0 < 320; k0 += 16) {
        float4 av = *(const float4*)(A + (size_t)(row0 + lr) * 320 + k0 + lk);
        As[lk + 0][lr] = av.x; As[lk + 1][lr] = av.y;
        As[lk + 2][lr] = av.z; As[lk + 3][lr] = av.w;
        *(float4*)&Bs[bk][bc] = *(const float4*)(B + (size_t)(k0 + bk) * 64 + bc);
        __syncthreads();
#pragma unroll
        for (int kk = 0; kk < 16; kk++) {
            float4 a4 = *(const float4*)&As[kk][ty * 4];
            float4 b4 = *(const float4*)&Bs[kk][tx * 4];
            float aa[4] = {a4.x, a4.y, a4.z, a4.w};
            float bb[4] = {b4.x, b4.y, b4.z, b4.w};
#pragma unroll
            for (int i = 0; i < 4; i++)
#pragma unroll
                for (int j = 0; j < 4; j++) acc[i][j] += aa[i] * bb[j];
        }
        __syncthreads();
    }
#pragma unroll
    for (int j = 0; j < 4; j++) {
        int o = tx * 4 + j;
        float sc = bn[o] * rsqrtf(bn[192 + o] + EPSB);
        float ofs = bn[64 + o] + (bias[o] - bn[128 + o]) * sc;
#pragma unroll
        for (int i = 0; i < 4; i++) {
            int r = row0 + ty * 4 + i;
            int b = r >= HW;
            int pp = r - b * HW;
            float y = acc[i][j] * sc + ofs;
            bev[(size_t)(b * 64 + o) * HW + pp] = fmaxf(y, 0.f);
        }
    }
}

__global__ void k_gemm_bev1(const float* __restrict__ A, const float* __restrict__ B,
                            const float* __restrict__ bias, const float* __restrict__ bn,
                            float* __restrict__ bev) {
    __shared__ float As[16][72];
    __shared__ float Bs[16][64];
    int tid = threadIdx.x;
    int tx = tid & 15, ty = tid >> 4;
    int row0 = blockIdx.x * 64;
    int colbase = blockIdx.y * 64;
    float acc[4][4] = {};
    int lr = tid >> 2, lk = (tid & 3) * 4;
    int bk = tid >> 4, bc = (tid & 15) * 4;
    for (int k0 = 0; k0 < 320; k0 += 16) {
        float4 av = *(const float4*)(A + (size_t)(row0 + lr) * 320 + k0 + lk);
        As[lk + 0][lr] = av.x; As[lk + 1][lr] = av.y;
        As[lk + 2][lr] = av.z; As[lk + 3][lr] = av.w;
        *(float4*)&Bs[bk][bc] = *(const float4*)(B + (size_t)(k0 + bk) * 256 + colbase + bc);
        __syncthreads();
#pragma unroll
        for (int kk = 0; kk < 16; kk++) {
            float4 a4 = *(const float4*)&As[kk][ty * 4];
            float4 b4 = *(const float4*)&Bs[kk][tx * 4];
            float aa[4] = {a4.x, a4.y, a4.z, a4.w};
            float bb[4] = {b4.x, b4.y, b4.z, b4.w};
#pragma unroll
            for (int i = 0; i < 4; i++)
#pragma unroll
                for (int j = 0; j < 4; j++) acc[i][j] += aa[i] * bb[j];
        }
        __syncthreads();
    }
    int ij = blockIdx.y, ii = ij >> 1, jj = ij & 1;
#pragma unroll
    for (int j = 0; j < 4; j++) {
        int o = tx * 4 + j;
        float sc = bn[o] * rsqrtf(bn[192 + o] + EPSB);
        float ofs = bn[64 + o] + (bias[o] - bn[128 + o]) * sc;
#pragma unroll
        for (int i = 0; i < 4; i++) {
            int r = row0 + ty * 4 + i;
            int b = r >= HW1;
            int p = r - b * HW1;
            int y = p / X1D, x = p - y * X1D;
            int opix = (2 * y + ii) * XD + 2 * x + jj;
            float val = acc[i][j] * sc + ofs;
            bev[(size_t)(b * 64 + o) * HW + opix] = fmaxf(val, 0.f);
        }
    }
}

// ---------------- per-pixel 2-agent attention fusion ----------------
__global__ void k_fusion(const float* __restrict__ bev, float* __restrict__ out, int cbase) {
    int p = blockIdx.x * blockDim.x + threadIdx.x;
    if (p >= HW) return;
    float l00 = 0.f, l01 = 0.f;
#pragma unroll 8
    for (int c = 0; c < 64; c++) {
        float x0 = bev[c * HW + p];
        float x1 = bev[(64 + c) * HW + p];
        l00 += x0 * x0;
        l01 += x0 * x1;
    }
    l00 *= 0.125f; l01 *= 0.125f;
    float mm = fmaxf(l00, l01);
    float e0 = expf(l00 - mm), e1 = expf(l01 - mm);
    float inv = 1.f / (e0 + e1);
    float a0 = e0 * inv, a1 = e1 * inv;
#pragma unroll 8
    for (int c = 0; c < 64; c++) {
        float x0 = bev[c * HW + p];
        float x1 = bev[(64 + c) * HW + p];
        out[(size_t)(cbase + c) * HW + p] = a0 * x0 + a1 * x1;
    }
}

// ---------------- host launcher (R8 layout) ----------------
static inline unsigned blocks_for(long long threads, int bs) {
    return (unsigned)((threads + bs - 1) / bs);
}

extern "C" void kernel_launch(void* const* d_in, const int* in_sizes, int n_in,
                              void* d_out, int out_size) {
    const float* sp    = (const float*)d_in[0];
    const float* w_in  = (const float*)d_in[1];
    const float* w0    = (const float*)d_in[2];
    const float* bnp0  = (const float*)d_in[3];
    const float* w0a   = (const float*)d_in[4];
    const float* bnp0a = (const float*)d_in[5];
    const float* w0b   = (const float*)d_in[6];
    const float* bnp0b = (const float*)d_in[7];
    const float* w1    = (const float*)d_in[8];
    const float* bnp1  = (const float*)d_in[9];
    const float* w1a   = (const float*)d_in[10];
    const float* bnp1a = (const float*)d_in[11];
    const float* w1b   = (const float*)d_in[12];
    const float* bnp1b = (const float*)d_in[13];
    const float* ct0_w = (const float*)d_in[14];
    const float* ct0_b = (const float*)d_in[15];
    const float* bnt0  = (const float*)d_in[16];
    const float* ct1_w = (const float*)d_in[17];
    const float* ct1_b = (const float*)d_in[18];
    const float* bnt1  = (const float*)d_in[19];
    const int* coords0 = (const int*)d_in[20];
    const int* coords1 = (const int*)d_in[21];
    const int* g0      = (const int*)d_in[22];
    const int* s0      = (const int*)d_in[23];
    const int* ga      = (const int*)d_in[24];
    const int* sa      = (const int*)d_in[25];
    const int* g1      = (const int*)d_in[26];
    const int* s1      = (const int*)d_in[27];
    const int* gb      = (const int*)d_in[28];
    const int* sb      = (const int*)d_in[29];
    float* out = (float*)d_out;

    float *fin, *f0a, *f0b, *f1a, *f1b, *d0, *d1, *bev0, *bev1, *w0p, *w1p;
    int* cnt;
    cudaGetSymbolAddress((void**)&fin,  g_fin);
    cudaGetSymbolAddress((void**)&f0a,  g_f0a);
    cudaGetSymbolAddress((void**)&f0b,  g_f0b);
    cudaGetSymbolAddress((void**)&f1a,  g_f1a);
    cudaGetSymbolAddress((void**)&f1b,  g_f1b);
    cudaGetSymbolAddress((void**)&d0,   g_d0);
    cudaGetSymbolAddress((void**)&d1,   g_d1);
    cudaGetSymbolAddress((void**)&bev0, g_bev0);
    cudaGetSymbolAddress((void**)&bev1, g_bev1);
    cudaGetSymbolAddress((void**)&w0p,  g_w0p);
    cudaGetSymbolAddress((void**)&w1p,  g_w1p);
    cudaGetSymbolAddress((void**)&cnt,  g_cnt);

    static cudaStream_t s1s = nullptr;
    static cudaEvent_t evFork = nullptr, evF0a = nullptr, evBev0 = nullptr;
    if (s1s == nullptr) {
        cudaStreamCreateWithFlags(&s1s, cudaStreamNonBlocking);
        cudaEventCreateWithFlags(&evFork, cudaEventDisableTiming);
        cudaEventCreateWithFlags(&evF0a, cudaEventDisableTiming);
        cudaEventCreateWithFlags(&evBev0, cudaEventDisableTiming);
    }

    const int BS = 256;

    // fork side stream for input-only work: d0 memset + conv1x1 weight permute
    cudaEventRecord(evFork, 0);
    cudaStreamWaitEvent(s1s, evFork, 0);
    cudaMemsetAsync(d0, 0, (size_t)2 * HW * 320 * sizeof(float), s1s);
    k_permw0<<<blocks_for(320 * 64, BS), BS, 0, s1s>>>(ct0_w, w0p);

    // main stream: counts, input GEMM, stage 0
    k_counts<<<1, 128>>>(s0, sa, s1, sb);
    k_gemm_in<<<blocks_for((long long)NIN * 32, BS), BS>>>(sp, w_in, fin);

    cudaMemsetAsync(f0a, 0, (size_t)(CAP0 + 1) * 32 * sizeof(float), 0);
    k_spconv32<false, 24><<<27 * 24, 256>>>(fin, g0, s0, w0, nullptr, f0a, NIN, cnt);

    cudaMemsetAsync(f0b, 0, (size_t)(CAP0 + 1) * 32 * sizeof(float), 0);
    k_spconv32<true, 48><<<27 * 48, 256>>>(f0a, ga, sa, w0a, bnp0, f0b, CAP0, cnt + 27);

    cudaMemsetAsync(f0a, 0, (size_t)(CAP0 + 1) * 32 * sizeof(float), 0);
    k_spconv32<true, 48><<<27 * 48, 256>>>(f0b, ga, sa, w0b, bnp0a, f0a, CAP0, cnt + 27);

    // f0a (pre-BN) ready: fork dense BEV0 path onto side stream
    cudaEventRecord(evF0a, 0);
    cudaStreamWaitEvent(s1s, evF0a, 0);
    k_scatter0<<<1184, 256, 0, s1s>>>(f0a, coords0, bnp0b, d0);
    k_gemm_bev0<<<(2 * HW) / 64, 256, 0, s1s>>>(d0, w0p, ct0_b, bnt0, bev0);
    k_fusion<<<blocks_for(HW, BS), BS, 0, s1s>>>(bev0, out, 0);
    cudaEventRecord(evBev0, s1s);

    // main stream: stage 1 spconvs run concurrently with BEV0 dense path
    cudaMemsetAsync(f1a, 0, (size_t)(CAP1 + 1) * 64 * sizeof(float), 0);
    k_spconv3264<true, 48><<<27 * 48, 256>>>(f0a, g1, s1, w1, bnp0b, f1a, CAP0, cnt + 54);

    cudaMemsetAsync(f1b, 0, (size_t)(CAP1 + 1) * 64 * sizeof(float), 0);
    k_spconv64<true, 192><<<27 * 192, 128>>>(f1a, gb, sb, w1a, bnp1, f1b, CAP1, cnt + 81);

    cudaMemsetAsync(f1a, 0, (size_t)(CAP1 + 1) * 64 * sizeof(float), 0);
    k_spconv64<true, 192><<<27 * 192, 128>>>(f1b, gb, sb, w1b, bnp1a, f1a, CAP1, cnt + 81);

    // dense BEV 1 on main stream
    cudaMemsetAsync(d1, 0, (size_t)2 * HW1 * 320 * sizeof(float), 0);
    k_scatter1<<<592, 256>>>(f1a, coords1, bnp1b, d1);
    k_permw1<<<blocks_for(320 * 256, BS), BS>>>(ct1_w, w1p);
    {
        dim3 grid((2 * HW1) / 64, 4);
        k_gemm_bev1<<<grid, 256>>>(d1, w1p, ct1_b, bnt1, bev1);
    }
    cudaStreamWaitEvent(0, evBev0, 0);
    k_fusion<<<blocks_for(HW, BS), BS>>>(bev1, out, 64);
}

// round 13
// speedup vs baseline: 1.1475x; 1.1475x over previous
#include <cuda_runtime.h>
#include <math.h>

// ---------------- problem constants ----------------
#define NIN    20000          // B_AG * N_PTS
#define CAP0   540000         // 27 * NIN
#define CAP1   352000         // B_AG * Z1*Y1*X1
#define ZD     10
#define YD     200
#define XD     704
#define Z1D    5
#define Y1D    100
#define X1D    352
#define HW     (YD*XD)        // 140800
#define HW1    (Y1D*X1D)      // 35200
#define EPSB   1e-5f

// ---------------- static device scratch ----------------
__device__ float g_fin [NIN * 32];
__device__ float g_f0a [(CAP0 + 1) * 32];
__device__ float g_f0b [(CAP0 + 1) * 32];
__device__ float g_f1a [(CAP1 + 1) * 64];
__device__ float g_f1b [(CAP1 + 1) * 64];
__device__ float g_d0  [2 * HW  * 320];              // [b*HW+p][z*32+c]
__device__ float g_d1  [2 * HW1 * 320];              // [b*HW1+p][z*64+c]
__device__ float g_w0p [320 * 64];
__device__ float g_w1p [320 * 256];
__device__ int   g_cnt [108];

// ---------------- packed f32x2 helpers ----------------
__device__ __forceinline__ void fma2(unsigned long long& acc, unsigned long long a,
                                     unsigned long long b) {
    asm("fma.rn.f32x2 %0, %1, %2, %0;" : "+l"(acc) : "l"(a), "l"(b));
}
__device__ __forceinline__ void lds_2x64(unsigned long long& a, unsigned long long& b,
                                         unsigned addr) {
    asm volatile("ld.shared.v2.b64 {%0, %1}, [%2];" : "=l"(a), "=l"(b) : "r"(addr));
}
__device__ __forceinline__ unsigned long long pack2(float x, float y) {
    unsigned long long r;
    asm("mov.b64 %0, {%1, %2};" : "=l"(r) : "f"(x), "f"(y));
    return r;
}
__device__ __forceinline__ float hsum2(unsigned long long a) {
    float x, y;
    asm("mov.b64 {%0, %1}, %2;" : "=f"(x), "=f"(y) : "l"(a));
    return x + y;
}
__device__ __forceinline__ void redv2(float* p, float a, float b) {
    asm volatile("red.global.add.v2.f32 [%0], {%1, %2};" :: "l"(p), "f"(a), "f"(b)
                 : "memory");
}

// ---------------- rulebook pair counts ----------------
__global__ void k_counts(const int* __restrict__ s0, const int* __restrict__ sa,
                         const int* __restrict__ s1, const int* __restrict__ sb) {
    int t = blockIdx.x * blockDim.x + threadIdx.x;
    if (t >= 108) return;
    int rb = t / 27, k = t % 27;
    const int* S; int pc, cap;
    if      (rb == 0) { S = s0; pc = NIN;  cap = CAP0; }
    else if (rb == 1) { S = sa; pc = CAP0; cap = CAP0; }
    else if (rb == 2) { S = s1; pc = CAP0; cap = CAP1; }
    else              { S = sb; pc = CAP1; cap = CAP1; }
    const int* row = S + (size_t)k * pc;
    int lo = 0, hi = pc;
    while (lo < hi) {
        int mid = (lo + hi) >> 1;
        if (row[mid] == cap) hi = mid; else lo = mid + 1;
    }
    g_cnt[t] = lo;
}

// ---------------- input GEMM ----------------
__global__ void k_gemm_in(const float* __restrict__ sp, const float* __restrict__ w,
                          float* __restrict__ out) {
    int t = blockIdx.x * blockDim.x + threadIdx.x;
    if (t >= NIN * 32) return;
    int i = t >> 5, j = t & 31;
    const float* r = sp + i * 64;
    float acc = 0.f;
#pragma unroll
    for (int c = 0; c < 64; c++) acc += r[c] * w[c * 32 + j];
    out[t] = acc;
}

// ---------------- spconv CIN=32 COUT=32 (R8) ----------------
template<bool BN, int NB>
__global__ void __launch_bounds__(256) k_spconv32(
    const float* __restrict__ feats, const int* __restrict__ G, const int* __restrict__ S,
    const float* __restrict__ W, const float* __restrict__ bn,
    float* __restrict__ out, int pair_cap, const int* __restrict__ cnt) {
    __shared__ float slot[8][2][2][32];
    int k = blockIdx.x / NB;
    int lane = threadIdx.x & 31;
    int warp = threadIdx.x >> 5;
    int half = lane >> 4;
    int j = lane & 15;
    const float* Wk = W + (size_t)k * 1024;
    unsigned long long wA[16], wB[16];
#pragma unroll
    for (int i = 0; i < 16; i++) {
        wA[i] = pack2(Wk[(2 * i) * 32 + 2 * j],     Wk[(2 * i + 1) * 32 + 2 * j]);
        wB[i] = pack2(Wk[(2 * i) * 32 + 2 * j + 1], Wk[(2 * i + 1) * 32 + 2 * j + 1]);
    }
    float sc[4] = {1.f,1.f,1.f,1.f}, of[4] = {0.f,0.f,0.f,0.f};
    if (BN && j < 8) {
#pragma unroll
        for (int c = 0; c < 4; c++) {
            int idx = 4 * j + c;
            sc[c] = bn[idx] * rsqrtf(bn[96 + idx] + EPSB);
            of[c] = bn[32 + idx] - bn[64 + idx] * sc[c];
        }
    }
    int n = cnt[k];
    const int* Gk = G + (size_t)k * pair_cap;
    const int* Sk = S + (size_t)k * pair_cap;
    int base = ((blockIdx.x % NB) * 8 + warp) * 2;
    const int stride = NB * 16;
    unsigned sa0 = (unsigned)__cvta_generic_to_shared(&slot[warp][0][half][0]);
    unsigned sa1 = (unsigned)__cvta_generic_to_shared(&slot[warp][1][half][0]);
    for (int pb = base; pb < n; pb += 2 * stride) {
        int p0 = pb + half, p1 = pb + stride + half;
        bool a0 = p0 < n, a1 = p1 < n;
        int g0 = 0, s0 = 0, g1 = 0, s1 = 0;
        if (a0) { g0 = Gk[p0]; s0 = Sk[p0]; }
        if (a1) { g1 = Gk[p1]; s1 = Sk[p1]; }
        float4 f0 = make_float4(0,0,0,0), f1 = make_float4(0,0,0,0);
        if (a0 && j < 8) f0 = *(const float4*)(feats + (size_t)g0 * 32 + 4 * j);
        if (a1 && j < 8) f1 = *(const float4*)(feats + (size_t)g1 * 32 + 4 * j);
        if (j < 8) {
            if (BN) {
                f0.x = fmaxf(f0.x * sc[0] + of[0], 0.f); f0.y = fmaxf(f0.y * sc[1] + of[1], 0.f);
                f0.z = fmaxf(f0.z * sc[2] + of[2], 0.f); f0.w = fmaxf(f0.w * sc[3] + of[3], 0.f);
                f1.x = fmaxf(f1.x * sc[0] + of[0], 0.f); f1.y = fmaxf(f1.y * sc[1] + of[1], 0.f);
                f1.z = fmaxf(f1.z * sc[2] + of[2], 0.f); f1.w = fmaxf(f1.w * sc[3] + of[3], 0.f);
            }
            if (a0) *(float4*)&slot[warp][0][half][4 * j] = f0;
            if (a1) *(float4*)&slot[warp][1][half][4 * j] = f1;
        }
        __syncwarp();
        unsigned long long A = 0ull, B = 0ull;
#pragma unroll
        for (int i = 0; i < 8; i++) {
            unsigned long long va, vb;
            lds_2x64(va, vb, sa0 + i * 16);
            fma2(A, va, wA[2 * i]); fma2(B, va, wB[2 * i]);
            fma2(A, vb, wA[2 * i + 1]); fma2(B, vb, wB[2 * i + 1]);
        }
        if (a0) redv2(out + (size_t)s0 * 32 + 2 * j, hsum2(A), hsum2(B));
        A = 0ull; B = 0ull;
#pragma unroll
        for (int i = 0; i < 8; i++) {
            unsigned long long va, vb;
            lds_2x64(va, vb, sa1 + i * 16);
            fma2(A, va, wA[2 * i]); fma2(B, va, wB[2 * i]);
            fma2(A, vb, wA[2 * i + 1]); fma2(B, vb, wB[2 * i + 1]);
        }
        if (a1) redv2(out + (size_t)s1 * 32 + 2 * j, hsum2(A), hsum2(B));
        __syncwarp();
    }
}

// ---------------- spconv CIN=32 COUT=64 (R8) ----------------
template<bool BN, int NB>
__global__ void __launch_bounds__(256) k_spconv3264(
    const float* __restrict__ feats, const int* __restrict__ G, const int* __restrict__ S,
    const float* __restrict__ W, const float* __restrict__ bn,
    float* __restrict__ out, int pair_cap, const int* __restrict__ cnt) {
    __shared__ float slot[8][2][32];
    int k = blockIdx.x / NB;
    int lane = threadIdx.x & 31;
    int warp = threadIdx.x >> 5;
    const float* Wk = W + (size_t)k * 2048;
    unsigned long long wA[16], wB[16];
#pragma unroll
    for (int i = 0; i < 16; i++) {
        wA[i] = pack2(Wk[(2 * i) * 64 + 2 * lane],     Wk[(2 * i + 1) * 64 + 2 * lane]);
        wB[i] = pack2(Wk[(2 * i) * 64 + 2 * lane + 1], Wk[(2 * i + 1) * 64 + 2 * lane + 1]);
    }
    float sc[4] = {1.f,1.f,1.f,1.f}, of[4] = {0.f,0.f,0.f,0.f};
    if (BN && lane < 8) {
#pragma unroll
        for (int c = 0; c < 4; c++) {
            int idx = 4 * lane + c;
            sc[c] = bn[idx] * rsqrtf(bn[96 + idx] + EPSB);
            of[c] = bn[32 + idx] - bn[64 + idx] * sc[c];
        }
    }
    int n = cnt[k];
    const int* Gk = G + (size_t)k * pair_cap;
    const int* Sk = S + (size_t)k * pair_cap;
    int base = (blockIdx.x % NB) * 8 + warp;
    const int stride = NB * 8;
    unsigned sa0 = (unsigned)__cvta_generic_to_shared(&slot[warp][0][0]);
    unsigned sa1 = (unsigned)__cvta_generic_to_shared(&slot[warp][1][0]);
    for (int p = base; p < n; p += 2 * stride) {
        int p1 = p + stride;
        bool a1 = p1 < n;
        int g0 = Gk[p], s0 = Sk[p], g1 = 0, s1 = 0;
        if (a1) { g1 = Gk[p1]; s1 = Sk[p1]; }
        float4 f0 = make_float4(0,0,0,0), f1 = make_float4(0,0,0,0);
        if (lane < 8) {
            f0 = *(const float4*)(feats + (size_t)g0 * 32 + 4 * lane);
            if (a1) f1 = *(const float4*)(feats + (size_t)g1 * 32 + 4 * lane);
            if (BN) {
                f0.x = fmaxf(f0.x * sc[0] + of[0], 0.f); f0.y = fmaxf(f0.y * sc[1] + of[1], 0.f);
                f0.z = fmaxf(f0.z * sc[2] + of[2], 0.f); f0.w = fmaxf(f0.w * sc[3] + of[3], 0.f);
                f1.x = fmaxf(f1.x * sc[0] + of[0], 0.f); f1.y = fmaxf(f1.y * sc[1] + of[1], 0.f);
                f1.z = fmaxf(f1.z * sc[2] + of[2], 0.f); f1.w = fmaxf(f1.w * sc[3] + of[3], 0.f);
            }
            *(float4*)&slot[warp][0][4 * lane] = f0;
            if (a1) *(float4*)&slot[warp][1][4 * lane] = f1;
        }
        __syncwarp();
        unsigned long long A = 0ull, B = 0ull;
#pragma unroll
        for (int i = 0; i < 8; i++) {
            unsigned long long va, vb;
            lds_2x64(va, vb, sa0 + i * 16);
            fma2(A, va, wA[2 * i]); fma2(B, va, wB[2 * i]);
            fma2(A, vb, wA[2 * i + 1]); fma2(B, vb, wB[2 * i + 1]);
        }
        redv2(out + (size_t)s0 * 64 + 2 * lane, hsum2(A), hsum2(B));
        if (a1) {
            A = 0ull; B = 0ull;
#pragma unroll
            for (int i = 0; i < 8; i++) {
                unsigned long long va, vb;
                lds_2x64(va, vb, sa1 + i * 16);
                fma2(A, va, wA[2 * i]); fma2(B, va, wB[2 * i]);
                fma2(A, vb, wA[2 * i + 1]); fma2(B, vb, wB[2 * i + 1]);
            }
            redv2(out + (size_t)s1 * 64 + 2 * lane, hsum2(A), hsum2(B));
        }
        __syncwarp();
    }
}

// ---------------- spconv CIN=64 COUT=64 (R8) ----------------
template<bool BN, int NB>
__global__ void __launch_bounds__(128) k_spconv64(
    const float* __restrict__ feats, const int* __restrict__ G, const int* __restrict__ S,
    const float* __restrict__ W, const float* __restrict__ bn,
    float* __restrict__ out, int pair_cap, const int* __restrict__ cnt) {
    __shared__ float slot[4][2][64];
    int k = blockIdx.x / NB;
    int lane = threadIdx.x & 31;
    int warp = threadIdx.x >> 5;
    const float* Wk = W + (size_t)k * 4096;
    unsigned long long wA[32], wB[32];
#pragma unroll
    for (int i = 0; i < 32; i++) {
        wA[i] = pack2(Wk[(2 * i) * 64 + 2 * lane],     Wk[(2 * i + 1) * 64 + 2 * lane]);
        wB[i] = pack2(Wk[(2 * i) * 64 + 2 * lane + 1], Wk[(2 * i + 1) * 64 + 2 * lane + 1]);
    }
    float sc0 = 1.f, of0 = 0.f, sc1 = 1.f, of1 = 0.f;
    if (BN) {
        int c0 = 2 * lane, c1 = 2 * lane + 1;
        sc0 = bn[c0] * rsqrtf(bn[192 + c0] + EPSB);
        of0 = bn[64 + c0] - bn[128 + c0] * sc0;
        sc1 = bn[c1] * rsqrtf(bn[192 + c1] + EPSB);
        of1 = bn[64 + c1] - bn[128 + c1] * sc1;
    }
    int n = cnt[k];
    const int* Gk = G + (size_t)k * pair_cap;
    const int* Sk = S + (size_t)k * pair_cap;
    int base = (blockIdx.x % NB) * 4 + warp;
    const int stride = NB * 4;
    unsigned sa0 = (unsigned)__cvta_generic_to_shared(&slot[warp][0][0]);
    unsigned sa1 = (unsigned)__cvta_generic_to_shared(&slot[warp][1][0]);
    for (int p = base; p < n; p += 2 * stride) {
        int p1 = p + stride;
        bool a1 = p1 < n;
        int g0 = Gk[p], s0 = Sk[p], g1 = 0, s1 = 0;
        if (a1) { g1 = Gk[p1]; s1 = Sk[p1]; }
        float2 f0 = *(const float2*)(feats + (size_t)g0 * 64 + 2 * lane);
        float2 f1 = make_float2(0.f, 0.f);
        if (a1) f1 = *(const float2*)(feats + (size_t)g1 * 64 + 2 * lane);
        if (BN) {
            f0.x = fmaxf(f0.x * sc0 + of0, 0.f); f0.y = fmaxf(f0.y * sc1 + of1, 0.f);
            f1.x = fmaxf(f1.x * sc0 + of0, 0.f); f1.y = fmaxf(f1.y * sc1 + of1, 0.f);
        }
        *(float2*)&slot[warp][0][2 * lane] = f0;
        if (a1) *(float2*)&slot[warp][1][2 * lane] = f1;
        __syncwarp();
        unsigned long long A = 0ull, B = 0ull;
#pragma unroll
        for (int i = 0; i < 16; i++) {
            unsigned long long va, vb;
            lds_2x64(va, vb, sa0 + i * 16);
            fma2(A, va, wA[2 * i]); fma2(B, va, wB[2 * i]);
            fma2(A, vb, wA[2 * i + 1]); fma2(B, vb, wB[2 * i + 1]);
        }
        redv2(out + (size_t)s0 * 64 + 2 * lane, hsum2(A), hsum2(B));
        if (a1) {
            A = 0ull; B = 0ull;
#pragma unroll
            for (int i = 0; i < 16; i++) {
                unsigned long long va, vb;
                lds_2x64(va, vb, sa1 + i * 16);
                fma2(A, va, wA[2 * i]); fma2(B, va, wB[2 * i]);
                fma2(A, vb, wA[2 * i + 1]); fma2(B, vb, wB[2 * i + 1]);
            }
            redv2(out + (size_t)s1 * 64 + 2 * lane, hsum2(A), hsum2(B));
        }
        __syncwarp();
    }
}

// ---------------- sparse -> dense scatter with fused BN+ReLU ----------------
__global__ void k_scatter0(const float* __restrict__ f, const int* __restrict__ co,
                           const float* __restrict__ bn, float* __restrict__ d0) {
    int lane = threadIdx.x & 31;
    float sc = bn[lane] * rsqrtf(bn[96 + lane] + EPSB);
    float of = bn[32 + lane] - bn[64 + lane] * sc;
    int warps_total = (gridDim.x * blockDim.x) >> 5;
    for (unsigned w = (blockIdx.x * blockDim.x + threadIdx.x) >> 5; w < CAP0;
         w += warps_total) {
        int z = co[4 * w + 1];
        if ((unsigned)z >= (unsigned)ZD) continue;
        int b = co[4 * w], y = co[4 * w + 2], x = co[4 * w + 3];
        size_t base = ((size_t)(b * HW + y * XD + x)) * 320 + z * 32;
        d0[base + lane] = fmaxf(f[(size_t)w * 32 + lane] * sc + of, 0.f);
    }
}

__global__ void k_scatter1(const float* __restrict__ f, const int* __restrict__ co,
                           const float* __restrict__ bn, float* __restrict__ d1) {
    int lane = threadIdx.x & 31;
    float scA = bn[lane] * rsqrtf(bn[192 + lane] + EPSB);
    float ofA = bn[64 + lane] - bn[128 + lane] * scA;
    float scB = bn[lane + 32] * rsqrtf(bn[192 + lane + 32] + EPSB);
    float ofB = bn[64 + lane + 32] - bn[128 + lane + 32] * scB;
    int warps_total = (gridDim.x * blockDim.x) >> 5;
    for (unsigned w = (blockIdx.x * blockDim.x + threadIdx.x) >> 5; w < CAP1;
         w += warps_total) {
        int z = co[4 * w + 1];
        if ((unsigned)z >= (unsigned)Z1D) continue;
        int b = co[4 * w], y = co[4 * w + 2], x = co[4 * w + 3];
        size_t base = ((size_t)(b * HW1 + y * X1D + x)) * 320 + z * 64;
        d1[base + lane]      = fmaxf(f[(size_t)w * 64 + lane] * scA + ofA, 0.f);
        d1[base + lane + 32] = fmaxf(f[(size_t)w * 64 + lane + 32] * scB + ofB, 0.f);
    }
}

// ---------------- weight permutes ----------------
__global__ void k_permw0(const float* __restrict__ w, float* __restrict__ wp) {
    int t = blockIdx.x * blockDim.x + threadIdx.x;
    if (t >= 320 * 64) return;
    int o = t & 63, kk = t >> 6;
    int z = kk >> 5, c = kk & 31;
    wp[t] = w[(c * 10 + z) * 64 + o];
}
__global__ void k_permw1(const float* __restrict__ w, float* __restrict__ wp) {
    int t = blockIdx.x * blockDim.x + threadIdx.x;
    if (t >= 320 * 256) return;
    int col = t & 255, kk = t >> 8;
    int ij = col >> 6, o = col & 63;
    int z = kk >> 6, c = kk & 63;
    wp[t] = w[((c * 5 + z) * 64 + o) * 4 + ij];
}

// ---------------- GEMM + BN + ReLU + 2-agent attention fusion, BEV0 ------------------
// Block = 32 pixels x 2 agents (64 A-rows) x 64 channels. Writes out[0..63] directly.
__global__ void k_gemm_bev0f(const float* __restrict__ A, const float* __restrict__ B,
                             const float* __restrict__ bias, const float* __restrict__ bn,
                             float* __restrict__ out) {
    __shared__ float As[16][72];
    __shared__ float Bs[16][64];
    __shared__ float Cs[64][65];
    __shared__ float w0s[32], w1s[32];
    int tid = threadIdx.x;
    int tx = tid & 15, ty = tid >> 4;
    int px0 = blockIdx.x * 32;
    float acc[4][4] = {};
    int lr = tid >> 2, lk = (tid & 3) * 4;
    int bk = tid >> 4, bc = (tid & 15) * 4;
    size_t arow = (lr < 32) ? (size_t)(px0 + lr) : (size_t)HW + px0 + (lr - 32);
    for (int k0 = 0; k0 < 320; k0 += 16) {
        float4 av = *(const float4*)(A + arow * 320 + k0 + lk);
        As[lk + 0][lr] = av.x; As[lk + 1][lr] = av.y;
        As[lk + 2][lr] = av.z; As[lk + 3][lr] = av.w;
        *(float4*)&Bs[bk][bc] = *(const float4*)(B + (size_t)(k0 + bk) * 64 + bc);
        __syncthreads();
#pragma unroll
        for (int kk = 0; kk < 16; kk++) {
            float4 a4 = *(const float4*)&As[kk][ty * 4];
            float4 b4 = *(const float4*)&Bs[kk][tx * 4];
            float aa[4] = {a4.x, a4.y, a4.z, a4.w};
            float bb[4] = {b4.x, b4.y, b4.z, b4.w};
#pragma unroll
            for (int i = 0; i < 4; i++)
#pragma unroll
                for (int j = 0; j < 4; j++) acc[i][j] += aa[i] * bb[j];
        }
        __syncthreads();
    }
#pragma unroll
    for (int j = 0; j < 4; j++) {
        int o = tx * 4 + j;
        float sc = bn[o] * rsqrtf(bn[192 + o] + EPSB);
        float ofs = bn[64 + o] + (bias[o] - bn[128 + o]) * sc;
#pragma unroll
        for (int i = 0; i < 4; i++)
            Cs[ty * 4 + i][o] = fmaxf(acc[i][j] * sc + ofs, 0.f);
    }
    __syncthreads();
    // per-pixel 2-agent attention (8 threads per pixel)
    {
        int q = tid >> 3, sub = tid & 7;
        float l00 = 0.f, l01 = 0.f;
#pragma unroll
        for (int c = sub * 8; c < sub * 8 + 8; c++) {
            float x0 = Cs[q][c], x1 = Cs[32 + q][c];
            l00 += x0 * x0; l01 += x0 * x1;
        }
#pragma unroll
        for (int m = 4; m; m >>= 1) {
            l00 += __shfl_xor_sync(0xffffffffu, l00, m);
            l01 += __shfl_xor_sync(0xffffffffu, l01, m);
        }
        if (sub == 0) {
            l00 *= 0.125f; l01 *= 0.125f;
            float mm = fmaxf(l00, l01);
            float e0 = expf(l00 - mm), e1 = expf(l01 - mm);
            float inv = 1.f / (e0 + e1);
            w0s[q] = e0 * inv; w1s[q] = e1 * inv;
        }
    }
    __syncthreads();
    {
        int q = tid & 31, cb = tid >> 5;
        float a0 = w0s[q], a1 = w1s[q];
#pragma unroll
        for (int it = 0; it < 8; it++) {
            int c = cb * 8 + it;
            out[(size_t)c * HW + px0 + q] = a0 * Cs[q][c] + a1 * Cs[32 + q][c];
        }
    }
}

// ---------------- GEMM(convT) + BN + ReLU + fusion, BEV1 -----------------------------
// Block = 32 input pixels x 2 agents, col tile = ij quadrant. Writes out[64..127].
__global__ void k_gemm_bev1f(const float* __restrict__ A, const float* __restrict__ B,
                             const float* __restrict__ bias, const float* __restrict__ bn,
                             float* __restrict__ out) {
    __shared__ float As[16][72];
    __shared__ float Bs[16][64];
    __shared__ float Cs[64][65];
    __shared__ float w0s[32], w1s[32];
    int tid = threadIdx.x;
    int tx = tid & 15, ty = tid >> 4;
    int px0 = blockIdx.x * 32;
    int colbase = blockIdx.y * 64;
    float acc[4][4] = {};
    int lr = tid >> 2, lk = (tid & 3) * 4;
    int bk = tid >> 4, bc = (tid & 15) * 4;
    size_t arow = (lr < 32) ? (size_t)(px0 + lr) : (size_t)HW1 + px0 + (lr - 32);
    for (int k0 = 0; k0 < 320; k0 += 16) {
        float4 av = *(const float4*)(A + arow * 320 + k0 + lk);
        As[lk + 0][lr] = av.x; As[lk + 1][lr] = av.y;
        As[lk + 2][lr] = av.z; As[lk + 3][lr] = av.w;
        *(float4*)&Bs[bk][bc] = *(const float4*)(B + (size_t)(k0 + bk) * 256 + colbase + bc);
        __syncthreads();
#pragma unroll
        for (int kk = 0; kk < 16; kk++) {
            float4 a4 = *(const float4*)&As[kk][ty * 4];
            float4 b4 = *(const float4*)&Bs[kk][tx * 4];
            float aa[4] = {a4.x, a4.y, a4.z, a4.w};
            float bb[4] = {b4.x, b4.y, b4.z, b4.w};
#pragma unroll
            for (int i = 0; i < 4; i++)
#pragma unroll
                for (int j = 0; j < 4; j++) acc[i][j] += aa[i] * bb[j];
        }
        __syncthreads();
    }
#pragma unroll
    for (int j = 0; j < 4; j++) {
        int o = tx * 4 + j;
        float sc = bn[o] * rsqrtf(bn[192 + o] + EPSB);
        float ofs = bn[64 + o] + (bias[o] - bn[128 + o]) * sc;
#pragma unroll
        for (int i = 0; i < 4; i++)
            Cs[ty * 4 + i][o] = fmaxf(acc[i][j] * sc + ofs, 0.f);
    }
    __syncthreads();
    {
        int q = tid >> 3, sub = tid & 7;
        float l00 = 0.f, l01 = 0.f;
#pragma unroll
        for (int c = sub * 8; c < sub * 8 + 8; c++) {
            float x0 = Cs[q][c], x1 = Cs[32 + q][c];
            l00 += x0 * x0; l01 += x0 * x1;
        }
#pragma unroll
        for (int m = 4; m; m >>= 1) {
            l00 += __shfl_xor_sync(0xffffffffu, l00, m);
            l01 += __shfl_xor_sync(0xffffffffu, l01, m);
        }
        if (sub == 0) {
            l00 *= 0.125f; l01 *= 0.125f;
            float mm = fmaxf(l00, l01);
            float e0 = expf(l00 - mm), e1 = expf(l01 - mm);
            float inv = 1.f / (e0 + e1);
            w0s[q] = e0 * inv; w1s[q] = e1 * inv;
        }
    }
    __syncthreads();
    {
        int ij = blockIdx.y, ii = ij >> 1, jj = ij & 1;
        int q = tid & 31, cb = tid >> 5;
        int ip = px0 + q;
        int y = ip / X1D, x = ip - y * X1D;
        size_t opix = (size_t)(2 * y + ii) * XD + 2 * x + jj;
        float a0 = w0s[q], a1 = w1s[q];
#pragma unroll
        for (int it = 0; it < 8; it++) {
            int c = cb * 8 + it;
            out[(size_t)(64 + c) * HW + opix] = a0 * Cs[q][c] + a1 * Cs[32 + q][c];
        }
    }
}

// ---------------- host launcher ----------------
static inline unsigned blocks_for(long long threads, int bs) {
    return (unsigned)((threads + bs - 1) / bs);
}

extern "C" void kernel_launch(void* const* d_in, const int* in_sizes, int n_in,
                              void* d_out, int out_size) {
    const float* sp    = (const float*)d_in[0];
    const float* w_in  = (const float*)d_in[1];
    const float* w0    = (const float*)d_in[2];
    const float* bnp0  = (const float*)d_in[3];
    const float* w0a   = (const float*)d_in[4];
    const float* bnp0a = (const float*)d_in[5];
    const float* w0b   = (const float*)d_in[6];
    const float* bnp0b = (const float*)d_in[7];
    const float* w1    = (const float*)d_in[8];
    const float* bnp1  = (const float*)d_in[9];
    const float* w1a   = (const float*)d_in[10];
    const float* bnp1a = (const float*)d_in[11];
    const float* w1b   = (const float*)d_in[12];
    const float* bnp1b = (const float*)d_in[13];
    const float* ct0_w = (const float*)d_in[14];
    const float* ct0_b = (const float*)d_in[15];
    const float* bnt0  = (const float*)d_in[16];
    const float* ct1_w = (const float*)d_in[17];
    const float* ct1_b = (const float*)d_in[18];
    const float* bnt1  = (const float*)d_in[19];
    const int* coords0 = (const int*)d_in[20];
    const int* coords1 = (const int*)d_in[21];
    const int* g0      = (const int*)d_in[22];
    const int* s0      = (const int*)d_in[23];
    const int* ga      = (const int*)d_in[24];
    const int* sa      = (const int*)d_in[25];
    const int* g1      = (const int*)d_in[26];
    const int* s1      = (const int*)d_in[27];
    const int* gb      = (const int*)d_in[28];
    const int* sb      = (const int*)d_in[29];
    float* out = (float*)d_out;

    float *fin, *f0a, *f0b, *f1a, *f1b, *d0, *d1, *w0p, *w1p;
    int* cnt;
    cudaGetSymbolAddress((void**)&fin,  g_fin);
    cudaGetSymbolAddress((void**)&f0a,  g_f0a);
    cudaGetSymbolAddress((void**)&f0b,  g_f0b);
    cudaGetSymbolAddress((void**)&f1a,  g_f1a);
    cudaGetSymbolAddress((void**)&f1b,  g_f1b);
    cudaGetSymbolAddress((void**)&d0,   g_d0);
    cudaGetSymbolAddress((void**)&d1,   g_d1);
    cudaGetSymbolAddress((void**)&w0p,  g_w0p);
    cudaGetSymbolAddress((void**)&w1p,  g_w1p);
    cudaGetSymbolAddress((void**)&cnt,  g_cnt);

    static cudaStream_t s1s = nullptr;
    static cudaEvent_t evFork = nullptr, evF0a = nullptr, evBev0 = nullptr,
                       evSide = nullptr;
    if (s1s == nullptr) {
        cudaStreamCreateWithFlags(&s1s, cudaStreamNonBlocking);
        cudaEventCreateWithFlags(&evFork, cudaEventDisableTiming);
        cudaEventCreateWithFlags(&evF0a, cudaEventDisableTiming);
        cudaEventCreateWithFlags(&evBev0, cudaEventDisableTiming);
        cudaEventCreateWithFlags(&evSide, cudaEventDisableTiming);
    }

    const int BS = 256;

    // fork: side stream does input-only work (d0/d1 memsets + both weight permutes)
    cudaEventRecord(evFork, 0);
    cudaStreamWaitEvent(s1s, evFork, 0);
    cudaMemsetAsync(d0, 0, (size_t)2 * HW * 320 * sizeof(float), s1s);
    cudaMemsetAsync(d1, 0, (size_t)2 * HW1 * 320 * sizeof(float), s1s);
    k_permw0<<<blocks_for(320 * 64, BS), BS, 0, s1s>>>(ct0_w, w0p);
    k_permw1<<<blocks_for(320 * 256, BS), BS, 0, s1s>>>(ct1_w, w1p);
    cudaEventRecord(evSide, s1s);

    // main stream: counts, input GEMM, stage 0
    k_counts<<<1, 128>>>(s0, sa, s1, sb);
    k_gemm_in<<<blocks_for((long long)NIN * 32, BS), BS>>>(sp, w_in, fin);

    cudaMemsetAsync(f0a, 0, (size_t)(CAP0 + 1) * 32 * sizeof(float), 0);
    k_spconv32<false, 24><<<27 * 24, 256>>>(fin, g0, s0, w0, nullptr, f0a, NIN, cnt);

    cudaMemsetAsync(f0b, 0, (size_t)(CAP0 + 1) * 32 * sizeof(float), 0);
    k_spconv32<true, 48><<<27 * 48, 256>>>(f0a, ga, sa, w0a, bnp0, f0b, CAP0, cnt + 27);

    cudaMemsetAsync(f0a, 0, (size_t)(CAP0 + 1) * 32 * sizeof(float), 0);
    k_spconv32<true, 48><<<27 * 48, 256>>>(f0b, ga, sa, w0b, bnp0a, f0a, CAP0, cnt + 27);

    // f0a ready: fork dense BEV0 path (scatter -> fused GEMM+fusion) onto side stream
    cudaEventRecord(evF0a, 0);
    cudaStreamWaitEvent(s1s, evF0a, 0);
    k_scatter0<<<1184, 256, 0, s1s>>>(f0a, coords0, bnp0b, d0);
    k_gemm_bev0f<<<HW / 32, 256, 0, s1s>>>(d0, w0p, ct0_b, bnt0, out);
    cudaEventRecord(evBev0, s1s);

    // main stream: stage 1 spconvs concurrent with BEV0 dense path
    cudaMemsetAsync(f1a, 0, (size_t)(CAP1 + 1) * 64 * sizeof(float), 0);
    k_spconv3264<true, 48><<<27 * 48, 256>>>(f0a, g1, s1, w1, bnp0b, f1a, CAP0, cnt + 54);

    cudaMemsetAsync(f1b, 0, (size_t)(CAP1 + 1) * 64 * sizeof(float), 0);
    k_spconv64<true, 96><<<27 * 96, 128>>>(f1a, gb, sb, w1a, bnp1, f1b, CAP1, cnt + 81);

    cudaMemsetAsync(f1a, 0, (size_t)(CAP1 + 1) * 64 * sizeof(float), 0);
    k_spconv64<true, 96><<<27 * 96, 128>>>(f1b, gb, sb, w1b, bnp1a, f1a, CAP1, cnt + 81);

    // dense BEV1 on main (d1 + w1p prepared on side stream at fork)
    cudaStreamWaitEvent(0, evSide, 0);
    k_scatter1<<<592, 256>>>(f1a, coords1, bnp1b, d1);
    cudaStreamWaitEvent(0, evBev0, 0);   // join side stream before final kernel
    {
        dim3 grid(HW1 / 32, 4);
        k_gemm_bev1f<<<grid, 256>>>(d1, w1p, ct1_b, bnt1, out);
    }
}

// round 14
// speedup vs baseline: 1.2088x; 1.0534x over previous
#include <cuda_runtime.h>
#include <math.h>

// ---------------- problem constants ----------------
#define NIN    20000          // B_AG * N_PTS
#define CAP0   540000         // 27 * NIN
#define CAP1   352000         // B_AG * Z1*Y1*X1
#define ZD     10
#define YD     200
#define XD     704
#define Z1D    5
#define Y1D    100
#define X1D    352
#define HW     (YD*XD)        // 140800
#define HW1    (Y1D*X1D)      // 35200
#define EPSB   1e-5f

// ---------------- static device scratch ----------------
__device__ float g_fin [NIN * 32];
__device__ float g_f0a [(CAP0 + 1) * 32];
__device__ float g_f0b [(CAP0 + 1) * 32];
__device__ float g_f1a [(CAP1 + 1) * 64];
__device__ float g_f1b [(CAP1 + 1) * 64];
__device__ float g_d0  [2 * HW  * 320];              // [b*HW+p][z*32+c]
__device__ float g_d1  [2 * HW1 * 320];              // [b*HW1+p][z*64+c]
__device__ float g_w0p [320 * 64];
__device__ float g_w1p [320 * 256];
__device__ int   g_cnt [108];

// ---------------- packed f32x2 helpers ----------------
__device__ __forceinline__ void fma2(unsigned long long& acc, unsigned long long a,
                                     unsigned long long b) {
    asm("fma.rn.f32x2 %0, %1, %2, %0;" : "+l"(acc) : "l"(a), "l"(b));
}
__device__ __forceinline__ void lds_2x64(unsigned long long& a, unsigned long long& b,
                                         unsigned addr) {
    asm volatile("ld.shared.v2.b64 {%0, %1}, [%2];" : "=l"(a), "=l"(b) : "r"(addr));
}
__device__ __forceinline__ unsigned long long pack2(float x, float y) {
    unsigned long long r;
    asm("mov.b64 %0, {%1, %2};" : "=l"(r) : "f"(x), "f"(y));
    return r;
}
__device__ __forceinline__ float hsum2(unsigned long long a) {
    float x, y;
    asm("mov.b64 {%0, %1}, %2;" : "=f"(x), "=f"(y) : "l"(a));
    return x + y;
}
__device__ __forceinline__ void redv2(float* p, float a, float b) {
    asm volatile("red.global.add.v2.f32 [%0], {%1, %2};" :: "l"(p), "f"(a), "f"(b)
                 : "memory");
}

// ---------------- rulebook pair counts ----------------
__global__ void k_counts(const int* __restrict__ s0, const int* __restrict__ sa,
                         const int* __restrict__ s1, const int* __restrict__ sb) {
    int t = blockIdx.x * blockDim.x + threadIdx.x;
    if (t >= 108) return;
    int rb = t / 27, k = t % 27;
    const int* S; int pc, cap;
    if      (rb == 0) { S = s0; pc = NIN;  cap = CAP0; }
    else if (rb == 1) { S = sa; pc = CAP0; cap = CAP0; }
    else if (rb == 2) { S = s1; pc = CAP0; cap = CAP1; }
    else              { S = sb; pc = CAP1; cap = CAP1; }
    const int* row = S + (size_t)k * pc;
    int lo = 0, hi = pc;
    while (lo < hi) {
        int mid = (lo + hi) >> 1;
        if (row[mid] == cap) hi = mid; else lo = mid + 1;
    }
    g_cnt[t] = lo;
}

// ---------------- input GEMM ----------------
__global__ void k_gemm_in(const float* __restrict__ sp, const float* __restrict__ w,
                          float* __restrict__ out) {
    int t = blockIdx.x * blockDim.x + threadIdx.x;
    if (t >= NIN * 32) return;
    int i = t >> 5, j = t & 31;
    const float* r = sp + i * 64;
    float acc = 0.f;
#pragma unroll
    for (int c = 0; c < 64; c++) acc += r[c] * w[c * 32 + j];
    out[t] = acc;
}

// ---------------- spconv CIN=32 COUT=32: 128-thread blocks, 2 pairs/warp -------------
template<bool BN, int NB>
__global__ void __launch_bounds__(128) k_spconv32(
    const float* __restrict__ feats, const int* __restrict__ G, const int* __restrict__ S,
    const float* __restrict__ W, const float* __restrict__ bn,
    float* __restrict__ out, int pair_cap, const int* __restrict__ cnt) {
    __shared__ float slot[4][2][2][32];
    int k = blockIdx.x / NB;
    int lane = threadIdx.x & 31;
    int warp = threadIdx.x >> 5;             // 0..3
    int half = lane >> 4;
    int j = lane & 15;
    const float* Wk = W + (size_t)k * 1024;
    unsigned long long wA[16], wB[16];
#pragma unroll
    for (int i = 0; i < 16; i++) {
        wA[i] = pack2(Wk[(2 * i) * 32 + 2 * j],     Wk[(2 * i + 1) * 32 + 2 * j]);
        wB[i] = pack2(Wk[(2 * i) * 32 + 2 * j + 1], Wk[(2 * i + 1) * 32 + 2 * j + 1]);
    }
    float sc[4] = {1.f,1.f,1.f,1.f}, of[4] = {0.f,0.f,0.f,0.f};
    if (BN && j < 8) {
#pragma unroll
        for (int c = 0; c < 4; c++) {
            int idx = 4 * j + c;
            sc[c] = bn[idx] * rsqrtf(bn[96 + idx] + EPSB);
            of[c] = bn[32 + idx] - bn[64 + idx] * sc[c];
        }
    }
    int n = cnt[k];
    const int* Gk = G + (size_t)k * pair_cap;
    const int* Sk = S + (size_t)k * pair_cap;
    int base = ((blockIdx.x % NB) * 4 + warp) * 2;
    const int stride = NB * 8;
    unsigned sa0 = (unsigned)__cvta_generic_to_shared(&slot[warp][0][half][0]);
    unsigned sa1 = (unsigned)__cvta_generic_to_shared(&slot[warp][1][half][0]);
    for (int pb = base; pb < n; pb += 2 * stride) {
        int p0 = pb + half, p1 = pb + stride + half;
        bool a0 = p0 < n, a1 = p1 < n;
        int g0 = 0, s0 = 0, g1 = 0, s1 = 0;
        if (a0) { g0 = Gk[p0]; s0 = Sk[p0]; }
        if (a1) { g1 = Gk[p1]; s1 = Sk[p1]; }
        float4 f0 = make_float4(0,0,0,0), f1 = make_float4(0,0,0,0);
        if (a0 && j < 8) f0 = *(const float4*)(feats + (size_t)g0 * 32 + 4 * j);
        if (a1 && j < 8) f1 = *(const float4*)(feats + (size_t)g1 * 32 + 4 * j);
        if (j < 8) {
            if (BN) {
                f0.x = fmaxf(f0.x * sc[0] + of[0], 0.f); f0.y = fmaxf(f0.y * sc[1] + of[1], 0.f);
                f0.z = fmaxf(f0.z * sc[2] + of[2], 0.f); f0.w = fmaxf(f0.w * sc[3] + of[3], 0.f);
                f1.x = fmaxf(f1.x * sc[0] + of[0], 0.f); f1.y = fmaxf(f1.y * sc[1] + of[1], 0.f);
                f1.z = fmaxf(f1.z * sc[2] + of[2], 0.f); f1.w = fmaxf(f1.w * sc[3] + of[3], 0.f);
            }
            if (a0) *(float4*)&slot[warp][0][half][4 * j] = f0;
            if (a1) *(float4*)&slot[warp][1][half][4 * j] = f1;
        }
        __syncwarp();
        unsigned long long A = 0ull, B = 0ull;
#pragma unroll
        for (int i = 0; i < 8; i++) {
            unsigned long long va, vb;
            lds_2x64(va, vb, sa0 + i * 16);
            fma2(A, va, wA[2 * i]); fma2(B, va, wB[2 * i]);
            fma2(A, vb, wA[2 * i + 1]); fma2(B, vb, wB[2 * i + 1]);
        }
        if (a0) redv2(out + (size_t)s0 * 32 + 2 * j, hsum2(A), hsum2(B));
        A = 0ull; B = 0ull;
#pragma unroll
        for (int i = 0; i < 8; i++) {
            unsigned long long va, vb;
            lds_2x64(va, vb, sa1 + i * 16);
            fma2(A, va, wA[2 * i]); fma2(B, va, wB[2 * i]);
            fma2(A, vb, wA[2 * i + 1]); fma2(B, vb, wB[2 * i + 1]);
        }
        if (a1) redv2(out + (size_t)s1 * 32 + 2 * j, hsum2(A), hsum2(B));
        __syncwarp();
    }
}

// ---------------- spconv CIN=32 COUT=64: 128-thread blocks, warp/pair ----------------
template<bool BN, int NB>
__global__ void __launch_bounds__(128) k_spconv3264(
    const float* __restrict__ feats, const int* __restrict__ G, const int* __restrict__ S,
    const float* __restrict__ W, const float* __restrict__ bn,
    float* __restrict__ out, int pair_cap, const int* __restrict__ cnt) {
    __shared__ float slot[4][2][32];
    int k = blockIdx.x / NB;
    int lane = threadIdx.x & 31;
    int warp = threadIdx.x >> 5;             // 0..3
    const float* Wk = W + (size_t)k * 2048;
    unsigned long long wA[16], wB[16];
#pragma unroll
    for (int i = 0; i < 16; i++) {
        wA[i] = pack2(Wk[(2 * i) * 64 + 2 * lane],     Wk[(2 * i + 1) * 64 + 2 * lane]);
        wB[i] = pack2(Wk[(2 * i) * 64 + 2 * lane + 1], Wk[(2 * i + 1) * 64 + 2 * lane + 1]);
    }
    float sc[4] = {1.f,1.f,1.f,1.f}, of[4] = {0.f,0.f,0.f,0.f};
    if (BN && lane < 8) {
#pragma unroll
        for (int c = 0; c < 4; c++) {
            int idx = 4 * lane + c;
            sc[c] = bn[idx] * rsqrtf(bn[96 + idx] + EPSB);
            of[c] = bn[32 + idx] - bn[64 + idx] * sc[c];
        }
    }
    int n = cnt[k];
    const int* Gk = G + (size_t)k * pair_cap;
    const int* Sk = S + (size_t)k * pair_cap;
    int base = (blockIdx.x % NB) * 4 + warp;
    const int stride = NB * 4;
    unsigned sa0 = (unsigned)__cvta_generic_to_shared(&slot[warp][0][0]);
    unsigned sa1 = (unsigned)__cvta_generic_to_shared(&slot[warp][1][0]);
    for (int p = base; p < n; p += 2 * stride) {
        int p1 = p + stride;
        bool a1 = p1 < n;
        int g0 = Gk[p], s0 = Sk[p], g1 = 0, s1 = 0;
        if (a1) { g1 = Gk[p1]; s1 = Sk[p1]; }
        float4 f0 = make_float4(0,0,0,0), f1 = make_float4(0,0,0,0);
        if (lane < 8) {
            f0 = *(const float4*)(feats + (size_t)g0 * 32 + 4 * lane);
            if (a1) f1 = *(const float4*)(feats + (size_t)g1 * 32 + 4 * lane);
            if (BN) {
                f0.x = fmaxf(f0.x * sc[0] + of[0], 0.f); f0.y = fmaxf(f0.y * sc[1] + of[1], 0.f);
                f0.z = fmaxf(f0.z * sc[2] + of[2], 0.f); f0.w = fmaxf(f0.w * sc[3] + of[3], 0.f);
                f1.x = fmaxf(f1.x * sc[0] + of[0], 0.f); f1.y = fmaxf(f1.y * sc[1] + of[1], 0.f);
                f1.z = fmaxf(f1.z * sc[2] + of[2], 0.f); f1.w = fmaxf(f1.w * sc[3] + of[3], 0.f);
            }
            *(float4*)&slot[warp][0][4 * lane] = f0;
            if (a1) *(float4*)&slot[warp][1][4 * lane] = f1;
        }
        __syncwarp();
        unsigned long long A = 0ull, B = 0ull;
#pragma unroll
        for (int i = 0; i < 8; i++) {
            unsigned long long va, vb;
            lds_2x64(va, vb, sa0 + i * 16);
            fma2(A, va, wA[2 * i]); fma2(B, va, wB[2 * i]);
            fma2(A, vb, wA[2 * i + 1]); fma2(B, vb, wB[2 * i + 1]);
        }
        redv2(out + (size_t)s0 * 64 + 2 * lane, hsum2(A), hsum2(B));
        if (a1) {
            A = 0ull; B = 0ull;
#pragma unroll
            for (int i = 0; i < 8; i++) {
                unsigned long long va, vb;
                lds_2x64(va, vb, sa1 + i * 16);
                fma2(A, va, wA[2 * i]); fma2(B, va, wB[2 * i]);
                fma2(A, vb, wA[2 * i + 1]); fma2(B, vb, wB[2 * i + 1]);
            }
            redv2(out + (size_t)s1 * 64 + 2 * lane, hsum2(A), hsum2(B));
        }
        __syncwarp();
    }
}

// ---------------- spconv CIN=64 COUT=64 (R8, unchanged) ----------------
template<bool BN, int NB>
__global__ void __launch_bounds__(128) k_spconv64(
    const float* __restrict__ feats, const int* __restrict__ G, const int* __restrict__ S,
    const float* __restrict__ W, const float* __restrict__ bn,
    float* __restrict__ out, int pair_cap, const int* __restrict__ cnt) {
    __shared__ float slot[4][2][64];
    int k = blockIdx.x / NB;
    int lane = threadIdx.x & 31;
    int warp = threadIdx.x >> 5;
    const float* Wk = W + (size_t)k * 4096;
    unsigned long long wA[32], wB[32];
#pragma unroll
    for (int i = 0; i < 32; i++) {
        wA[i] = pack2(Wk[(2 * i) * 64 + 2 * lane],     Wk[(2 * i + 1) * 64 + 2 * lane]);
        wB[i] = pack2(Wk[(2 * i) * 64 + 2 * lane + 1], Wk[(2 * i + 1) * 64 + 2 * lane + 1]);
    }
    float sc0 = 1.f, of0 = 0.f, sc1 = 1.f, of1 = 0.f;
    if (BN) {
        int c0 = 2 * lane, c1 = 2 * lane + 1;
        sc0 = bn[c0] * rsqrtf(bn[192 + c0] + EPSB);
        of0 = bn[64 + c0] - bn[128 + c0] * sc0;
        sc1 = bn[c1] * rsqrtf(bn[192 + c1] + EPSB);
        of1 = bn[64 + c1] - bn[128 + c1] * sc1;
    }
    int n = cnt[k];
    const int* Gk = G + (size_t)k * pair_cap;
    const int* Sk = S + (size_t)k * pair_cap;
    int base = (blockIdx.x % NB) * 4 + warp;
    const int stride = NB * 4;
    unsigned sa0 = (unsigned)__cvta_generic_to_shared(&slot[warp][0][0]);
    unsigned sa1 = (unsigned)__cvta_generic_to_shared(&slot[warp][1][0]);
    for (int p = base; p < n; p += 2 * stride) {
        int p1 = p + stride;
        bool a1 = p1 < n;
        int g0 = Gk[p], s0 = Sk[p], g1 = 0, s1 = 0;
        if (a1) { g1 = Gk[p1]; s1 = Sk[p1]; }
        float2 f0 = *(const float2*)(feats + (size_t)g0 * 64 + 2 * lane);
        float2 f1 = make_float2(0.f, 0.f);
        if (a1) f1 = *(const float2*)(feats + (size_t)g1 * 64 + 2 * lane);
        if (BN) {
            f0.x = fmaxf(f0.x * sc0 + of0, 0.f); f0.y = fmaxf(f0.y * sc1 + of1, 0.f);
            f1.x = fmaxf(f1.x * sc0 + of0, 0.f); f1.y = fmaxf(f1.y * sc1 + of1, 0.f);
        }
        *(float2*)&slot[warp][0][2 * lane] = f0;
        if (a1) *(float2*)&slot[warp][1][2 * lane] = f1;
        __syncwarp();
        unsigned long long A = 0ull, B = 0ull;
#pragma unroll
        for (int i = 0; i < 16; i++) {
            unsigned long long va, vb;
            lds_2x64(va, vb, sa0 + i * 16);
            fma2(A, va, wA[2 * i]); fma2(B, va, wB[2 * i]);
            fma2(A, vb, wA[2 * i + 1]); fma2(B, vb, wB[2 * i + 1]);
        }
        redv2(out + (size_t)s0 * 64 + 2 * lane, hsum2(A), hsum2(B));
        if (a1) {
            A = 0ull; B = 0ull;
#pragma unroll
            for (int i = 0; i < 16; i++) {
                unsigned long long va, vb;
                lds_2x64(va, vb, sa1 + i * 16);
                fma2(A, va, wA[2 * i]); fma2(B, va, wB[2 * i]);
                fma2(A, vb, wA[2 * i + 1]); fma2(B, vb, wB[2 * i + 1]);
            }
            redv2(out + (size_t)s1 * 64 + 2 * lane, hsum2(A), hsum2(B));
        }
        __syncwarp();
    }
}

// ---------------- sparse -> dense scatter with fused BN+ReLU ----------------
__global__ void k_scatter0(const float* __restrict__ f, const int* __restrict__ co,
                           const float* __restrict__ bn, float* __restrict__ d0) {
    int lane = threadIdx.x & 31;
    float sc = bn[lane] * rsqrtf(bn[96 + lane] + EPSB);
    float of = bn[32 + lane] - bn[64 + lane] * sc;
    int warps_total = (gridDim.x * blockDim.x) >> 5;
    for (unsigned w = (blockIdx.x * blockDim.x + threadIdx.x) >> 5; w < CAP0;
         w += warps_total) {
        int z = co[4 * w + 1];
        if ((unsigned)z >= (unsigned)ZD) continue;
        int b = co[4 * w], y = co[4 * w + 2], x = co[4 * w + 3];
        size_t base = ((size_t)(b * HW + y * XD + x)) * 320 + z * 32;
        d0[base + lane] = fmaxf(f[(size_t)w * 32 + lane] * sc + of, 0.f);
    }
}

__global__ void k_scatter1(const float* __restrict__ f, const int* __restrict__ co,
                           const float* __restrict__ bn, float* __restrict__ d1) {
    int lane = threadIdx.x & 31;
    float scA = bn[lane] * rsqrtf(bn[192 + lane] + EPSB);
    float ofA = bn[64 + lane] - bn[128 + lane] * scA;
    float scB = bn[lane + 32] * rsqrtf(bn[192 + lane + 32] + EPSB);
    float ofB = bn[64 + lane + 32] - bn[128 + lane + 32] * scB;
    int warps_total = (gridDim.x * blockDim.x) >> 5;
    for (unsigned w = (blockIdx.x * blockDim.x + threadIdx.x) >> 5; w < CAP1;
         w += warps_total) {
        int z = co[4 * w + 1];
        if ((unsigned)z >= (unsigned)Z1D) continue;
        int b = co[4 * w], y = co[4 * w + 2], x = co[4 * w + 3];
        size_t base = ((size_t)(b * HW1 + y * X1D + x)) * 320 + z * 64;
        d1[base + lane]      = fmaxf(f[(size_t)w * 64 + lane] * scA + ofA, 0.f);
        d1[base + lane + 32] = fmaxf(f[(size_t)w * 64 + lane + 32] * scB + ofB, 0.f);
    }
}

// ---------------- weight permutes ----------------
__global__ void k_permw0(const float* __restrict__ w, float* __restrict__ wp) {
    int t = blockIdx.x * blockDim.x + threadIdx.x;
    if (t >= 320 * 64) return;
    int o = t & 63, kk = t >> 6;
    int z = kk >> 5, c = kk & 31;
    wp[t] = w[(c * 10 + z) * 64 + o];
}
__global__ void k_permw1(const float* __restrict__ w, float* __restrict__ wp) {
    int t = blockIdx.x * blockDim.x + threadIdx.x;
    if (t >= 320 * 256) return;
    int col = t & 255, kk = t >> 8;
    int ij = col >> 6, o = col & 63;
    int z = kk >> 6, c = kk & 63;
    wp[t] = w[((c * 5 + z) * 64 + o) * 4 + ij];
}

// ---------------- GEMM + BN + ReLU + 2-agent attention fusion, BEV0 ------------------
__global__ void k_gemm_bev0f(const float* __restrict__ A, const float* __restrict__ B,
                             const float* __restrict__ bias, const float* __restrict__ bn,
                             float* __restrict__ out) {
    __shared__ float As[16][72];
    __shared__ float Bs[16][64];
    __shared__ float Cs[64][65];
    __shared__ float w0s[32], w1s[32];
    int tid = threadIdx.x;
    int tx = tid & 15, ty = tid >> 4;
    int px0 = blockIdx.x * 32;
    float acc[4][4] = {};
    int lr = tid >> 2, lk = (tid & 3) * 4;
    int bk = tid >> 4, bc = (tid & 15) * 4;
    size_t arow = (lr < 32) ? (size_t)(px0 + lr) : (size_t)HW + px0 + (lr - 32);
    for (int k0 = 0; k0 < 320; k0 += 16) {
        float4 av = *(const float4*)(A + arow * 320 + k0 + lk);
        As[lk + 0][lr] = av.x; As[lk + 1][lr] = av.y;
        As[lk + 2][lr] = av.z; As[lk + 3][lr] = av.w;
        *(float4*)&Bs[bk][bc] = *(const float4*)(B + (size_t)(k0 + bk) * 64 + bc);
        __syncthreads();
#pragma unroll
        for (int kk = 0; kk < 16; kk++) {
            float4 a4 = *(const float4*)&As[kk][ty * 4];
            float4 b4 = *(const float4*)&Bs[kk][tx * 4];
            float aa[4] = {a4.x, a4.y, a4.z, a4.w};
            float bb[4] = {b4.x, b4.y, b4.z, b4.w};
#pragma unroll
            for (int i = 0; i < 4; i++)
#pragma unroll
                for (int j = 0; j < 4; j++) acc[i][j] += aa[i] * bb[j];
        }
        __syncthreads();
    }
#pragma unroll
    for (int j = 0; j < 4; j++) {
        int o = tx * 4 + j;
        float sc = bn[o] * rsqrtf(bn[192 + o] + EPSB);
        float ofs = bn[64 + o] + (bias[o] - bn[128 + o]) * sc;
#pragma unroll
        for (int i = 0; i < 4; i++)
            Cs[ty * 4 + i][o] = fmaxf(acc[i][j] * sc + ofs, 0.f);
    }
    __syncthreads();
    {
        int q = tid >> 3, sub = tid & 7;
        float l00 = 0.f, l01 = 0.f;
#pragma unroll
        for (int c = sub * 8; c < sub * 8 + 8; c++) {
            float x0 = Cs[q][c], x1 = Cs[32 + q][c];
            l00 += x0 * x0; l01 += x0 * x1;
        }
#pragma unroll
        for (int m = 4; m; m >>= 1) {
            l00 += __shfl_xor_sync(0xffffffffu, l00, m);
            l01 += __shfl_xor_sync(0xffffffffu, l01, m);
        }
        if (sub == 0) {
            l00 *= 0.125f; l01 *= 0.125f;
            float mm = fmaxf(l00, l01);
            float e0 = expf(l00 - mm), e1 = expf(l01 - mm);
            float inv = 1.f / (e0 + e1);
            w0s[q] = e0 * inv; w1s[q] = e1 * inv;
        }
    }
    __syncthreads();
    {
        int q = tid & 31, cb = tid >> 5;
        float a0 = w0s[q], a1 = w1s[q];
#pragma unroll
        for (int it = 0; it < 8; it++) {
            int c = cb * 8 + it;
            out[(size_t)c * HW + px0 + q] = a0 * Cs[q][c] + a1 * Cs[32 + q][c];
        }
    }
}

// ---------------- GEMM(convT) + BN + ReLU + fusion, BEV1 -----------------------------
__global__ void k_gemm_bev1f(const float* __restrict__ A, const float* __restrict__ B,
                             const float* __restrict__ bias, const float* __restrict__ bn,
                             float* __restrict__ out) {
    __shared__ float As[16][72];
    __shared__ float Bs[16][64];
    __shared__ float Cs[64][65];
    __shared__ float w0s[32], w1s[32];
    int tid = threadIdx.x;
    int tx = tid & 15, ty = tid >> 4;
    int px0 = blockIdx.x * 32;
    int colbase = blockIdx.y * 64;
    float acc[4][4] = {};
    int lr = tid >> 2, lk = (tid & 3) * 4;
    int bk = tid >> 4, bc = (tid & 15) * 4;
    size_t arow = (lr < 32) ? (size_t)(px0 + lr) : (size_t)HW1 + px0 + (lr - 32);
    for (int k0 = 0; k0 < 320; k0 += 16) {
        float4 av = *(const float4*)(A + arow * 320 + k0 + lk);
        As[lk + 0][lr] = av.x; As[lk + 1][lr] = av.y;
        As[lk + 2][lr] = av.z; As[lk + 3][lr] = av.w;
        *(float4*)&Bs[bk][bc] = *(const float4*)(B + (size_t)(k0 + bk) * 256 + colbase + bc);
        __syncthreads();
#pragma unroll
        for (int kk = 0; kk < 16; kk++) {
            float4 a4 = *(const float4*)&As[kk][ty * 4];
            float4 b4 = *(const float4*)&Bs[kk][tx * 4];
            float aa[4] = {a4.x, a4.y, a4.z, a4.w};
            float bb[4] = {b4.x, b4.y, b4.z, b4.w};
#pragma unroll
            for (int i = 0; i < 4; i++)
#pragma unroll
                for (int j = 0; j < 4; j++) acc[i][j] += aa[i] * bb[j];
        }
        __syncthreads();
    }
#pragma unroll
    for (int j = 0; j < 4; j++) {
        int o = tx * 4 + j;
        float sc = bn[o] * rsqrtf(bn[192 + o] + EPSB);
        float ofs = bn[64 + o] + (bias[o] - bn[128 + o]) * sc;
#pragma unroll
        for (int i = 0; i < 4; i++)
            Cs[ty * 4 + i][o] = fmaxf(acc[i][j] * sc + ofs, 0.f);
    }
    __syncthreads();
    {
        int q = tid >> 3, sub = tid & 7;
        float l00 = 0.f, l01 = 0.f;
#pragma unroll
        for (int c = sub * 8; c < sub * 8 + 8; c++) {
            float x0 = Cs[q][c], x1 = Cs[32 + q][c];
            l00 += x0 * x0; l01 += x0 * x1;
        }
#pragma unroll
        for (int m = 4; m; m >>= 1) {
            l00 += __shfl_xor_sync(0xffffffffu, l00, m);
            l01 += __shfl_xor_sync(0xffffffffu, l01, m);
        }
        if (sub == 0) {
            l00 *= 0.125f; l01 *= 0.125f;
            float mm = fmaxf(l00, l01);
            float e0 = expf(l00 - mm), e1 = expf(l01 - mm);
            float inv = 1.f / (e0 + e1);
            w0s[q] = e0 * inv; w1s[q] = e1 * inv;
        }
    }
    __syncthreads();
    {
        int ij = blockIdx.y, ii = ij >> 1, jj = ij & 1;
        int q = tid & 31, cb = tid >> 5;
        int ip = px0 + q;
        int y = ip / X1D, x = ip - y * X1D;
        size_t opix = (size_t)(2 * y + ii) * XD + 2 * x + jj;
        float a0 = w0s[q], a1 = w1s[q];
#pragma unroll
        for (int it = 0; it < 8; it++) {
            int c = cb * 8 + it;
            out[(size_t)(64 + c) * HW + opix] = a0 * Cs[q][c] + a1 * Cs[32 + q][c];
        }
    }
}

// ---------------- host launcher ----------------
static inline unsigned blocks_for(long long threads, int bs) {
    return (unsigned)((threads + bs - 1) / bs);
}

extern "C" void kernel_launch(void* const* d_in, const int* in_sizes, int n_in,
                              void* d_out, int out_size) {
    const float* sp    = (const float*)d_in[0];
    const float* w_in  = (const float*)d_in[1];
    const float* w0    = (const float*)d_in[2];
    const float* bnp0  = (const float*)d_in[3];
    const float* w0a   = (const float*)d_in[4];
    const float* bnp0a = (const float*)d_in[5];
    const float* w0b   = (const float*)d_in[6];
    const float* bnp0b = (const float*)d_in[7];
    const float* w1    = (const float*)d_in[8];
    const float* bnp1  = (const float*)d_in[9];
    const float* w1a   = (const float*)d_in[10];
    const float* bnp1a = (const float*)d_in[11];
    const float* w1b   = (const float*)d_in[12];
    const float* bnp1b = (const float*)d_in[13];
    const float* ct0_w = (const float*)d_in[14];
    const float* ct0_b = (const float*)d_in[15];
    const float* bnt0  = (const float*)d_in[16];
    const float* ct1_w = (const float*)d_in[17];
    const float* ct1_b = (const float*)d_in[18];
    const float* bnt1  = (const float*)d_in[19];
    const int* coords0 = (const int*)d_in[20];
    const int* coords1 = (const int*)d_in[21];
    const int* g0      = (const int*)d_in[22];
    const int* s0      = (const int*)d_in[23];
    const int* ga      = (const int*)d_in[24];
    const int* sa      = (const int*)d_in[25];
    const int* g1      = (const int*)d_in[26];
    const int* s1      = (const int*)d_in[27];
    const int* gb      = (const int*)d_in[28];
    const int* sb      = (const int*)d_in[29];
    float* out = (float*)d_out;

    float *fin, *f0a, *f0b, *f1a, *f1b, *d0, *d1, *w0p, *w1p;
    int* cnt;
    cudaGetSymbolAddress((void**)&fin,  g_fin);
    cudaGetSymbolAddress((void**)&f0a,  g_f0a);
    cudaGetSymbolAddress((void**)&f0b,  g_f0b);
    cudaGetSymbolAddress((void**)&f1a,  g_f1a);
    cudaGetSymbolAddress((void**)&f1b,  g_f1b);
    cudaGetSymbolAddress((void**)&d0,   g_d0);
    cudaGetSymbolAddress((void**)&d1,   g_d1);
    cudaGetSymbolAddress((void**)&w0p,  g_w0p);
    cudaGetSymbolAddress((void**)&w1p,  g_w1p);
    cudaGetSymbolAddress((void**)&cnt,  g_cnt);

    static cudaStream_t s1s = nullptr;
    static cudaEvent_t evFork = nullptr, evF0a = nullptr, evBev0 = nullptr,
                       evSide = nullptr;
    if (s1s == nullptr) {
        cudaStreamCreateWithFlags(&s1s, cudaStreamNonBlocking);
        cudaEventCreateWithFlags(&evFork, cudaEventDisableTiming);
        cudaEventCreateWithFlags(&evF0a, cudaEventDisableTiming);
        cudaEventCreateWithFlags(&evBev0, cudaEventDisableTiming);
        cudaEventCreateWithFlags(&evSide, cudaEventDisableTiming);
    }

    const int BS = 256;

    // fork: side stream does input-only work (d0/d1 memsets + both weight permutes)
    cudaEventRecord(evFork, 0);
    cudaStreamWaitEvent(s1s, evFork, 0);
    cudaMemsetAsync(d0, 0, (size_t)2 * HW * 320 * sizeof(float), s1s);
    cudaMemsetAsync(d1, 0, (size_t)2 * HW1 * 320 * sizeof(float), s1s);
    k_permw0<<<blocks_for(320 * 64, BS), BS, 0, s1s>>>(ct0_w, w0p);
    k_permw1<<<blocks_for(320 * 256, BS), BS, 0, s1s>>>(ct1_w, w1p);
    cudaEventRecord(evSide, s1s);

    // main stream: counts, input GEMM, stage 0
    k_counts<<<1, 128>>>(s0, sa, s1, sb);
    k_gemm_in<<<blocks_for((long long)NIN * 32, BS), BS>>>(sp, w_in, fin);

    cudaMemsetAsync(f0a, 0, (size_t)(CAP0 + 1) * 32 * sizeof(float), 0);
    k_spconv32<false, 48><<<27 * 48, 128>>>(fin, g0, s0, w0, nullptr, f0a, NIN, cnt);

    cudaMemsetAsync(f0b, 0, (size_t)(CAP0 + 1) * 32 * sizeof(float), 0);
    k_spconv32<true, 96><<<27 * 96, 128>>>(f0a, ga, sa, w0a, bnp0, f0b, CAP0, cnt + 27);

    cudaMemsetAsync(f0a, 0, (size_t)(CAP0 + 1) * 32 * sizeof(float), 0);
    k_spconv32<true, 96><<<27 * 96, 128>>>(f0b, ga, sa, w0b, bnp0a, f0a, CAP0, cnt + 27);

    // f0a ready: fork dense BEV0 path (scatter -> fused GEMM+fusion) onto side stream
    cudaEventRecord(evF0a, 0);
    cudaStreamWaitEvent(s1s, evF0a, 0);
    k_scatter0<<<1184, 256, 0, s1s>>>(f0a, coords0, bnp0b, d0);
    k_gemm_bev0f<<<HW / 32, 256, 0, s1s>>>(d0, w0p, ct0_b, bnt0, out);
    cudaEventRecord(evBev0, s1s);

    // main stream: stage 1 spconvs concurrent with BEV0 dense path
    cudaMemsetAsync(f1a, 0, (size_t)(CAP1 + 1) * 64 * sizeof(float), 0);
    k_spconv3264<true, 96><<<27 * 96, 128>>>(f0a, g1, s1, w1, bnp0b, f1a, CAP0, cnt + 54);

    cudaMemsetAsync(f1b, 0, (size_t)(CAP1 + 1) * 64 * sizeof(float), 0);
    k_spconv64<true, 96><<<27 * 96, 128>>>(f1a, gb, sb, w1a, bnp1, f1b, CAP1, cnt + 81);

    cudaMemsetAsync(f1a, 0, (size_t)(CAP1 + 1) * 64 * sizeof(float), 0);
    k_spconv64<true, 96><<<27 * 96, 128>>>(f1b, gb, sb, w1b, bnp1a, f1a, CAP1, cnt + 81);

    // dense BEV1 on main (d1 + w1p prepared on side stream at fork)
    cudaStreamWaitEvent(0, evSide, 0);
    k_scatter1<<<592, 256>>>(f1a, coords1, bnp1b, d1);
    cudaStreamWaitEvent(0, evBev0, 0);   // join side stream before final kernel
    {
        dim3 grid(HW1 / 32, 4);
        k_gemm_bev1f<<<grid, 256>>>(d1, w1p, ct1_b, bnt1, out);
    }
}

// round 15
// speedup vs baseline: 1.2177x; 1.0073x over previous
#include <cuda_runtime.h>
#include <math.h>

// ---------------- problem constants ----------------
#define NIN    20000          // B_AG * N_PTS
#define CAP0   540000         // 27 * NIN
#define CAP1   352000         // B_AG * Z1*Y1*X1
#define ZD     10
#define YD     200
#define XD     704
#define Z1D    5
#define Y1D    100
#define X1D    352
#define HW     (YD*XD)        // 140800
#define HW1    (Y1D*X1D)      // 35200
#define EPSB   1e-5f

// ---------------- static device scratch ----------------
__device__ float g_fin [NIN * 32];
__device__ float g_f0a [(CAP0 + 1) * 32];
__device__ float g_f0b [(CAP0 + 1) * 32];
__device__ float g_f1a [(CAP1 + 1) * 64];
__device__ float g_f1b [(CAP1 + 1) * 64];
__device__ float g_d0  [2 * HW  * 320];              // [b*HW+p][z*32+c]
__device__ float g_d1  [2 * HW1 * 320];              // [b*HW1+p][z*64+c]
__device__ float g_w0p [320 * 64];
__device__ float g_w1p [320 * 256];
__device__ int   g_cnt [108];

// ---------------- packed f32x2 helpers ----------------
__device__ __forceinline__ void fma2(unsigned long long& acc, unsigned long long a,
                                     unsigned long long b) {
    asm("fma.rn.f32x2 %0, %1, %2, %0;" : "+l"(acc) : "l"(a), "l"(b));
}
__device__ __forceinline__ void lds_2x64(unsigned long long& a, unsigned long long& b,
                                         unsigned addr) {
    asm volatile("ld.shared.v2.b64 {%0, %1}, [%2];" : "=l"(a), "=l"(b) : "r"(addr));
}
__device__ __forceinline__ unsigned long long pack2(float x, float y) {
    unsigned long long r;
    asm("mov.b64 %0, {%1, %2};" : "=l"(r) : "f"(x), "f"(y));
    return r;
}
__device__ __forceinline__ float hsum2(unsigned long long a) {
    float x, y;
    asm("mov.b64 {%0, %1}, %2;" : "=f"(x), "=f"(y) : "l"(a));
    return x + y;
}
__device__ __forceinline__ void redv2(float* p, float a, float b) {
    asm volatile("red.global.add.v2.f32 [%0], {%1, %2};" :: "l"(p), "f"(a), "f"(b)
                 : "memory");
}

// ---------------- rulebook pair counts ----------------
__global__ void k_counts(const int* __restrict__ s0, const int* __restrict__ sa,
                         const int* __restrict__ s1, const int* __restrict__ sb) {
    int t = blockIdx.x * blockDim.x + threadIdx.x;
    if (t >= 108) return;
    int rb = t / 27, k = t % 27;
    const int* S; int pc, cap;
    if      (rb == 0) { S = s0; pc = NIN;  cap = CAP0; }
    else if (rb == 1) { S = sa; pc = CAP0; cap = CAP0; }
    else if (rb == 2) { S = s1; pc = CAP0; cap = CAP1; }
    else              { S = sb; pc = CAP1; cap = CAP1; }
    const int* row = S + (size_t)k * pc;
    int lo = 0, hi = pc;
    while (lo < hi) {
        int mid = (lo + hi) >> 1;
        if (row[mid] == cap) hi = mid; else lo = mid + 1;
    }
    g_cnt[t] = lo;
}

// ---------------- input GEMM ----------------
__global__ void k_gemm_in(const float* __restrict__ sp, const float* __restrict__ w,
                          float* __restrict__ out) {
    int t = blockIdx.x * blockDim.x + threadIdx.x;
    if (t >= NIN * 32) return;
    int i = t >> 5, j = t & 31;
    const float* r = sp + i * 64;
    float acc = 0.f;
#pragma unroll
    for (int c = 0; c < 64; c++) acc += r[c] * w[c * 32 + j];
    out[t] = acc;
}

// ---------------- spconv CIN=32 COUT=32: 128-thread blocks, 2 pairs/warp -------------
template<bool BN, int NB>
__global__ void __launch_bounds__(128) k_spconv32(
    const float* __restrict__ feats, const int* __restrict__ G, const int* __restrict__ S,
    const float* __restrict__ W, const float* __restrict__ bn,
    float* __restrict__ out, int pair_cap, const int* __restrict__ cnt) {
    __shared__ float slot[4][2][2][32];
    int k = blockIdx.x / NB;
    int lane = threadIdx.x & 31;
    int warp = threadIdx.x >> 5;             // 0..3
    int half = lane >> 4;
    int j = lane & 15;
    const float* Wk = W + (size_t)k * 1024;
    unsigned long long wA[16], wB[16];
#pragma unroll
    for (int i = 0; i < 16; i++) {
        wA[i] = pack2(Wk[(2 * i) * 32 + 2 * j],     Wk[(2 * i + 1) * 32 + 2 * j]);
        wB[i] = pack2(Wk[(2 * i) * 32 + 2 * j + 1], Wk[(2 * i + 1) * 32 + 2 * j + 1]);
    }
    float sc[4] = {1.f,1.f,1.f,1.f}, of[4] = {0.f,0.f,0.f,0.f};
    if (BN && j < 8) {
#pragma unroll
        for (int c = 0; c < 4; c++) {
            int idx = 4 * j + c;
            sc[c] = bn[idx] * rsqrtf(bn[96 + idx] + EPSB);
            of[c] = bn[32 + idx] - bn[64 + idx] * sc[c];
        }
    }
    int n = cnt[k];
    const int* Gk = G + (size_t)k * pair_cap;
    const int* Sk = S + (size_t)k * pair_cap;
    int base = ((blockIdx.x % NB) * 4 + warp) * 2;
    const int stride = NB * 8;
    unsigned sa0 = (unsigned)__cvta_generic_to_shared(&slot[warp][0][half][0]);
    unsigned sa1 = (unsigned)__cvta_generic_to_shared(&slot[warp][1][half][0]);
    for (int pb = base; pb < n; pb += 2 * stride) {
        int p0 = pb + half, p1 = pb + stride + half;
        bool a0 = p0 < n, a1 = p1 < n;
        int g0 = 0, s0 = 0, g1 = 0, s1 = 0;
        if (a0) { g0 = Gk[p0]; s0 = Sk[p0]; }
        if (a1) { g1 = Gk[p1]; s1 = Sk[p1]; }
        float4 f0 = make_float4(0,0,0,0), f1 = make_float4(0,0,0,0);
        if (a0 && j < 8) f0 = *(const float4*)(feats + (size_t)g0 * 32 + 4 * j);
        if (a1 && j < 8) f1 = *(const float4*)(feats + (size_t)g1 * 32 + 4 * j);
        if (j < 8) {
            if (BN) {
                f0.x = fmaxf(f0.x * sc[0] + of[0], 0.f); f0.y = fmaxf(f0.y * sc[1] + of[1], 0.f);
                f0.z = fmaxf(f0.z * sc[2] + of[2], 0.f); f0.w = fmaxf(f0.w * sc[3] + of[3], 0.f);
                f1.x = fmaxf(f1.x * sc[0] + of[0], 0.f); f1.y = fmaxf(f1.y * sc[1] + of[1], 0.f);
                f1.z = fmaxf(f1.z * sc[2] + of[2], 0.f); f1.w = fmaxf(f1.w * sc[3] + of[3], 0.f);
            }
            if (a0) *(float4*)&slot[warp][0][half][4 * j] = f0;
            if (a1) *(float4*)&slot[warp][1][half][4 * j] = f1;
        }
        __syncwarp();
        unsigned long long A = 0ull, B = 0ull;
#pragma unroll
        for (int i = 0; i < 8; i++) {
            unsigned long long va, vb;
            lds_2x64(va, vb, sa0 + i * 16);
            fma2(A, va, wA[2 * i]); fma2(B, va, wB[2 * i]);
            fma2(A, vb, wA[2 * i + 1]); fma2(B, vb, wB[2 * i + 1]);
        }
        if (a0) redv2(out + (size_t)s0 * 32 + 2 * j, hsum2(A), hsum2(B));
        A = 0ull; B = 0ull;
#pragma unroll
        for (int i = 0; i < 8; i++) {
            unsigned long long va, vb;
            lds_2x64(va, vb, sa1 + i * 16);
            fma2(A, va, wA[2 * i]); fma2(B, va, wB[2 * i]);
            fma2(A, vb, wA[2 * i + 1]); fma2(B, vb, wB[2 * i + 1]);
        }
        if (a1) redv2(out + (size_t)s1 * 32 + 2 * j, hsum2(A), hsum2(B));
        __syncwarp();
    }
}

// ---------------- spconv CIN=32 COUT=64: 128-thread blocks, warp/pair ----------------
template<bool BN, int NB>
__global__ void __launch_bounds__(128) k_spconv3264(
    const float* __restrict__ feats, const int* __restrict__ G, const int* __restrict__ S,
    const float* __restrict__ W, const float* __restrict__ bn,
    float* __restrict__ out, int pair_cap, const int* __restrict__ cnt) {
    __shared__ float slot[4][2][32];
    int k = blockIdx.x / NB;
    int lane = threadIdx.x & 31;
    int warp = threadIdx.x >> 5;             // 0..3
    const float* Wk = W + (size_t)k * 2048;
    unsigned long long wA[16], wB[16];
#pragma unroll
    for (int i = 0; i < 16; i++) {
        wA[i] = pack2(Wk[(2 * i) * 64 + 2 * lane],     Wk[(2 * i + 1) * 64 + 2 * lane]);
        wB[i] = pack2(Wk[(2 * i) * 64 + 2 * lane + 1], Wk[(2 * i + 1) * 64 + 2 * lane + 1]);
    }
    float sc[4] = {1.f,1.f,1.f,1.f}, of[4] = {0.f,0.f,0.f,0.f};
    if (BN && lane < 8) {
#pragma unroll
        for (int c = 0; c < 4; c++) {
            int idx = 4 * lane + c;
            sc[c] = bn[idx] * rsqrtf(bn[96 + idx] + EPSB);
            of[c] = bn[32 + idx] - bn[64 + idx] * sc[c];
        }
    }
    int n = cnt[k];
    const int* Gk = G + (size_t)k * pair_cap;
    const int* Sk = S + (size_t)k * pair_cap;
    int base = (blockIdx.x % NB) * 4 + warp;
    const int stride = NB * 4;
    unsigned sa0 = (unsigned)__cvta_generic_to_shared(&slot[warp][0][0]);
    unsigned sa1 = (unsigned)__cvta_generic_to_shared(&slot[warp][1][0]);
    for (int p = base; p < n; p += 2 * stride) {
        int p1 = p + stride;
        bool a1 = p1 < n;
        int g0 = Gk[p], s0 = Sk[p], g1 = 0, s1 = 0;
        if (a1) { g1 = Gk[p1]; s1 = Sk[p1]; }
        float4 f0 = make_float4(0,0,0,0), f1 = make_float4(0,0,0,0);
        if (lane < 8) {
            f0 = *(const float4*)(feats + (size_t)g0 * 32 + 4 * lane);
            if (a1) f1 = *(const float4*)(feats + (size_t)g1 * 32 + 4 * lane);
            if (BN) {
                f0.x = fmaxf(f0.x * sc[0] + of[0], 0.f); f0.y = fmaxf(f0.y * sc[1] + of[1], 0.f);
                f0.z = fmaxf(f0.z * sc[2] + of[2], 0.f); f0.w = fmaxf(f0.w * sc[3] + of[3], 0.f);
                f1.x = fmaxf(f1.x * sc[0] + of[0], 0.f); f1.y = fmaxf(f1.y * sc[1] + of[1], 0.f);
                f1.z = fmaxf(f1.z * sc[2] + of[2], 0.f); f1.w = fmaxf(f1.w * sc[3] + of[3], 0.f);
            }
            *(float4*)&slot[warp][0][4 * lane] = f0;
            if (a1) *(float4*)&slot[warp][1][4 * lane] = f1;
        }
        __syncwarp();
        unsigned long long A = 0ull, B = 0ull;
#pragma unroll
        for (int i = 0; i < 8; i++) {
            unsigned long long va, vb;
            lds_2x64(va, vb, sa0 + i * 16);
            fma2(A, va, wA[2 * i]); fma2(B, va, wB[2 * i]);
            fma2(A, vb, wA[2 * i + 1]); fma2(B, vb, wB[2 * i + 1]);
        }
        redv2(out + (size_t)s0 * 64 + 2 * lane, hsum2(A), hsum2(B));
        if (a1) {
            A = 0ull; B = 0ull;
#pragma unroll
            for (int i = 0; i < 8; i++) {
                unsigned long long va, vb;
                lds_2x64(va, vb, sa1 + i * 16);
                fma2(A, va, wA[2 * i]); fma2(B, va, wB[2 * i]);
                fma2(A, vb, wA[2 * i + 1]); fma2(B, vb, wB[2 * i + 1]);
            }
            redv2(out + (size_t)s1 * 64 + 2 * lane, hsum2(A), hsum2(B));
        }
        __syncwarp();
    }
}

// ---------------- spconv CIN=64 COUT=64: 64-thread blocks, warp/pair -----------------
template<bool BN, int NB>
__global__ void __launch_bounds__(64) k_spconv64(
    const float* __restrict__ feats, const int* __restrict__ G, const int* __restrict__ S,
    const float* __restrict__ W, const float* __restrict__ bn,
    float* __restrict__ out, int pair_cap, const int* __restrict__ cnt) {
    __shared__ float slot[2][2][64];
    int k = blockIdx.x / NB;
    int lane = threadIdx.x & 31;
    int warp = threadIdx.x >> 5;             // 0..1
    const float* Wk = W + (size_t)k * 4096;
    unsigned long long wA[32], wB[32];
#pragma unroll
    for (int i = 0; i < 32; i++) {
        wA[i] = pack2(Wk[(2 * i) * 64 + 2 * lane],     Wk[(2 * i + 1) * 64 + 2 * lane]);
        wB[i] = pack2(Wk[(2 * i) * 64 + 2 * lane + 1], Wk[(2 * i + 1) * 64 + 2 * lane + 1]);
    }
    float sc0 = 1.f, of0 = 0.f, sc1 = 1.f, of1 = 0.f;
    if (BN) {
        int c0 = 2 * lane, c1 = 2 * lane + 1;
        sc0 = bn[c0] * rsqrtf(bn[192 + c0] + EPSB);
        of0 = bn[64 + c0] - bn[128 + c0] * sc0;
        sc1 = bn[c1] * rsqrtf(bn[192 + c1] + EPSB);
        of1 = bn[64 + c1] - bn[128 + c1] * sc1;
    }
    int n = cnt[k];
    const int* Gk = G + (size_t)k * pair_cap;
    const int* Sk = S + (size_t)k * pair_cap;
    int base = (blockIdx.x % NB) * 2 + warp;
    const int stride = NB * 2;
    unsigned sa0 = (unsigned)__cvta_generic_to_shared(&slot[warp][0][0]);
    unsigned sa1 = (unsigned)__cvta_generic_to_shared(&slot[warp][1][0]);
    for (int p = base; p < n; p += 2 * stride) {
        int p1 = p + stride;
        bool a1 = p1 < n;
        int g0 = Gk[p], s0 = Sk[p], g1 = 0, s1 = 0;
        if (a1) { g1 = Gk[p1]; s1 = Sk[p1]; }
        float2 f0 = *(const float2*)(feats + (size_t)g0 * 64 + 2 * lane);
        float2 f1 = make_float2(0.f, 0.f);
        if (a1) f1 = *(const float2*)(feats + (size_t)g1 * 64 + 2 * lane);
        if (BN) {
            f0.x = fmaxf(f0.x * sc0 + of0, 0.f); f0.y = fmaxf(f0.y * sc1 + of1, 0.f);
            f1.x = fmaxf(f1.x * sc0 + of0, 0.f); f1.y = fmaxf(f1.y * sc1 + of1, 0.f);
        }
        *(float2*)&slot[warp][0][2 * lane] = f0;
        if (a1) *(float2*)&slot[warp][1][2 * lane] = f1;
        __syncwarp();
        unsigned long long A = 0ull, B = 0ull;
#pragma unroll
        for (int i = 0; i < 16; i++) {
            unsigned long long va, vb;
            lds_2x64(va, vb, sa0 + i * 16);
            fma2(A, va, wA[2 * i]); fma2(B, va, wB[2 * i]);
            fma2(A, vb, wA[2 * i + 1]); fma2(B, vb, wB[2 * i + 1]);
        }
        redv2(out + (size_t)s0 * 64 + 2 * lane, hsum2(A), hsum2(B));
        if (a1) {
            A = 0ull; B = 0ull;
#pragma unroll
            for (int i = 0; i < 16; i++) {
                unsigned long long va, vb;
                lds_2x64(va, vb, sa1 + i * 16);
                fma2(A, va, wA[2 * i]); fma2(B, va, wB[2 * i]);
                fma2(A, vb, wA[2 * i + 1]); fma2(B, vb, wB[2 * i + 1]);
            }
            redv2(out + (size_t)s1 * 64 + 2 * lane, hsum2(A), hsum2(B));
        }
        __syncwarp();
    }
}

// ---------------- sparse -> dense scatter with fused BN+ReLU ----------------
__global__ void k_scatter0(const float* __restrict__ f, const int* __restrict__ co,
                           const float* __restrict__ bn, float* __restrict__ d0) {
    int lane = threadIdx.x & 31;
    float sc = bn[lane] * rsqrtf(bn[96 + lane] + EPSB);
    float of = bn[32 + lane] - bn[64 + lane] * sc;
    int warps_total = (gridDim.x * blockDim.x) >> 5;
    for (unsigned w = (blockIdx.x * blockDim.x + threadIdx.x) >> 5; w < CAP0;
         w += warps_total) {
        int z = co[4 * w + 1];
        if ((unsigned)z >= (unsigned)ZD) continue;
        int b = co[4 * w], y = co[4 * w + 2], x = co[4 * w + 3];
        size_t base = ((size_t)(b * HW + y * XD + x)) * 320 + z * 32;
        d0[base + lane] = fmaxf(f[(size_t)w * 32 + lane] * sc + of, 0.f);
    }
}

__global__ void k_scatter1(const float* __restrict__ f, const int* __restrict__ co,
                           const float* __restrict__ bn, float* __restrict__ d1) {
    int lane = threadIdx.x & 31;
    float scA = bn[lane] * rsqrtf(bn[192 + lane] + EPSB);
    float ofA = bn[64 + lane] - bn[128 + lane] * scA;
    float scB = bn[lane + 32] * rsqrtf(bn[192 + lane + 32] + EPSB);
    float ofB = bn[64 + lane + 32] - bn[128 + lane + 32] * scB;
    int warps_total = (gridDim.x * blockDim.x) >> 5;
    for (unsigned w = (blockIdx.x * blockDim.x + threadIdx.x) >> 5; w < CAP1;
         w += warps_total) {
        int z = co[4 * w + 1];
        if ((unsigned)z >= (unsigned)Z1D) continue;
        int b = co[4 * w], y = co[4 * w + 2], x = co[4 * w + 3];
        size_t base = ((size_t)(b * HW1 + y * X1D + x)) * 320 + z * 64;
        d1[base + lane]      = fmaxf(f[(size_t)w * 64 + lane] * scA + ofA, 0.f);
        d1[base + lane + 32] = fmaxf(f[(size_t)w * 64 + lane + 32] * scB + ofB, 0.f);
    }
}

// ---------------- weight permutes ----------------
__global__ void k_permw0(const float* __restrict__ w, float* __restrict__ wp) {
    int t = blockIdx.x * blockDim.x + threadIdx.x;
    if (t >= 320 * 64) return;
    int o = t & 63, kk = t >> 6;
    int z = kk >> 5, c = kk & 31;
    wp[t] = w[(c * 10 + z) * 64 + o];
}
__global__ void k_permw1(const float* __restrict__ w, float* __restrict__ wp) {
    int t = blockIdx.x * blockDim.x + threadIdx.x;
    if (t >= 320 * 256) return;
    int col = t & 255, kk = t >> 8;
    int ij = col >> 6, o = col & 63;
    int z = kk >> 6, c = kk & 63;
    wp[t] = w[((c * 5 + z) * 64 + o) * 4 + ij];
}

// ---------------- GEMM + BN + ReLU + 2-agent attention fusion, BEV0 ------------------
__global__ void k_gemm_bev0f(const float* __restrict__ A, const float* __restrict__ B,
                             const float* __restrict__ bias, const float* __restrict__ bn,
                             float* __restrict__ out) {
    __shared__ float As[16][72];
    __shared__ float Bs[16][64];
    __shared__ float Cs[64][65];
    __shared__ float w0s[32], w1s[32];
    int tid = threadIdx.x;
    int tx = tid & 15, ty = tid >> 4;
    int px0 = blockIdx.x * 32;
    float acc[4][4] = {};
    int lr = tid >> 2, lk = (tid & 3) * 4;
    int bk = tid >> 4, bc = (tid & 15) * 4;
    size_t arow = (lr < 32) ? (size_t)(px0 + lr) : (size_t)HW + px0 + (lr - 32);
    for (int k0 = 0; k0 < 320; k0 += 16) {
        float4 av = *(const float4*)(A + arow * 320 + k0 + lk);
        As[lk + 0][lr] = av.x; As[lk + 1][lr] = av.y;
        As[lk + 2][lr] = av.z; As[lk + 3][lr] = av.w;
        *(float4*)&Bs[bk][bc] = *(const float4*)(B + (size_t)(k0 + bk) * 64 + bc);
        __syncthreads();
#pragma unroll
        for (int kk = 0; kk < 16; kk++) {
            float4 a4 = *(const float4*)&As[kk][ty * 4];
            float4 b4 = *(const float4*)&Bs[kk][tx * 4];
            float aa[4] = {a4.x, a4.y, a4.z, a4.w};
            float bb[4] = {b4.x, b4.y, b4.z, b4.w};
#pragma unroll
            for (int i = 0; i < 4; i++)
#pragma unroll
                for (int j = 0; j < 4; j++) acc[i][j] += aa[i] * bb[j];
        }
        __syncthreads();
    }
#pragma unroll
    for (int j = 0; j < 4; j++) {
        int o = tx * 4 + j;
        float sc = bn[o] * rsqrtf(bn[192 + o] + EPSB);
        float ofs = bn[64 + o] + (bias[o] - bn[128 + o]) * sc;
#pragma unroll
        for (int i = 0; i < 4; i++)
            Cs[ty * 4 + i][o] = fmaxf(acc[i][j] * sc + ofs, 0.f);
    }
    __syncthreads();
    {
        int q = tid >> 3, sub = tid & 7;
        float l00 = 0.f, l01 = 0.f;
#pragma unroll
        for (int c = sub * 8; c < sub * 8 + 8; c++) {
            float x0 = Cs[q][c], x1 = Cs[32 + q][c];
            l00 += x0 * x0; l01 += x0 * x1;
        }
#pragma unroll
        for (int m = 4; m; m >>= 1) {
            l00 += __shfl_xor_sync(0xffffffffu, l00, m);
            l01 += __shfl_xor_sync(0xffffffffu, l01, m);
        }
        if (sub == 0) {
            l00 *= 0.125f; l01 *= 0.125f;
            float mm = fmaxf(l00, l01);
            float e0 = expf(l00 - mm), e1 = expf(l01 - mm);
            float inv = 1.f / (e0 + e1);
            w0s[q] = e0 * inv; w1s[q] = e1 * inv;
        }
    }
    __syncthreads();
    {
        int q = tid & 31, cb = tid >> 5;
        float a0 = w0s[q], a1 = w1s[q];
#pragma unroll
        for (int it = 0; it < 8; it++) {
            int c = cb * 8 + it;
            out[(size_t)c * HW + px0 + q] = a0 * Cs[q][c] + a1 * Cs[32 + q][c];
        }
    }
}

// ---------------- GEMM(convT) + BN + ReLU + fusion, BEV1 -----------------------------
__global__ void k_gemm_bev1f(const float* __restrict__ A, const float* __restrict__ B,
                             const float* __restrict__ bias, const float* __restrict__ bn,
                             float* __restrict__ out) {
    __shared__ float As[16][72];
    __shared__ float Bs[16][64];
    __shared__ float Cs[64][65];
    __shared__ float w0s[32], w1s[32];
    int tid = threadIdx.x;
    int tx = tid & 15, ty = tid >> 4;
    int px0 = blockIdx.x * 32;
    int colbase = blockIdx.y * 64;
    float acc[4][4] = {};
    int lr = tid >> 2, lk = (tid & 3) * 4;
    int bk = tid >> 4, bc = (tid & 15) * 4;
    size_t arow = (lr < 32) ? (size_t)(px0 + lr) : (size_t)HW1 + px0 + (lr - 32);
    for (int k0 = 0; k0 < 320; k0 += 16) {
        float4 av = *(const float4*)(A + arow * 320 + k0 + lk);
        As[lk + 0][lr] = av.x; As[lk + 1][lr] = av.y;
        As[lk + 2][lr] = av.z; As[lk + 3][lr] = av.w;
        *(float4*)&Bs[bk][bc] = *(const float4*)(B + (size_t)(k0 + bk) * 256 + colbase + bc);
        __syncthreads();
#pragma unroll
        for (int kk = 0; kk < 16; kk++) {
            float4 a4 = *(const float4*)&As[kk][ty * 4];
            float4 b4 = *(const float4*)&Bs[kk][tx * 4];
            float aa[4] = {a4.x, a4.y, a4.z, a4.w};
            float bb[4] = {b4.x, b4.y, b4.z, b4.w};
#pragma unroll
            for (int i = 0; i < 4; i++)
#pragma unroll
                for (int j = 0; j < 4; j++) acc[i][j] += aa[i] * bb[j];
        }
        __syncthreads();
    }
#pragma unroll
    for (int j = 0; j < 4; j++) {
        int o = tx * 4 + j;
        float sc = bn[o] * rsqrtf(bn[192 + o] + EPSB);
        float ofs = bn[64 + o] + (bias[o] - bn[128 + o]) * sc;
#pragma unroll
        for (int i = 0; i < 4; i++)
            Cs[ty * 4 + i][o] = fmaxf(acc[i][j] * sc + ofs, 0.f);
    }
    __syncthreads();
    {
        int q = tid >> 3, sub = tid & 7;
        float l00 = 0.f, l01 = 0.f;
#pragma unroll
        for (int c = sub * 8; c < sub * 8 + 8; c++) {
            float x0 = Cs[q][c], x1 = Cs[32 + q][c];
            l00 += x0 * x0; l01 += x0 * x1;
        }
#pragma unroll
        for (int m = 4; m; m >>= 1) {
            l00 += __shfl_xor_sync(0xffffffffu, l00, m);
            l01 += __shfl_xor_sync(0xffffffffu, l01, m);
        }
        if (sub == 0) {
            l00 *= 0.125f; l01 *= 0.125f;
            float mm = fmaxf(l00, l01);
            float e0 = expf(l00 - mm), e1 = expf(l01 - mm);
            float inv = 1.f / (e0 + e1);
            w0s[q] = e0 * inv; w1s[q] = e1 * inv;
        }
    }
    __syncthreads();
    {
        int ij = blockIdx.y, ii = ij >> 1, jj = ij & 1;
        int q = tid & 31, cb = tid >> 5;
        int ip = px0 + q;
        int y = ip / X1D, x = ip - y * X1D;
        size_t opix = (size_t)(2 * y + ii) * XD + 2 * x + jj;
        float a0 = w0s[q], a1 = w1s[q];
#pragma unroll
        for (int it = 0; it < 8; it++) {
            int c = cb * 8 + it;
            out[(size_t)(64 + c) * HW + opix] = a0 * Cs[q][c] + a1 * Cs[32 + q][c];
        }
    }
}

// ---------------- host launcher ----------------
static inline unsigned blocks_for(long long threads, int bs) {
    return (unsigned)((threads + bs - 1) / bs);
}

extern "C" void kernel_launch(void* const* d_in, const int* in_sizes, int n_in,
                              void* d_out, int out_size) {
    const float* sp    = (const float*)d_in[0];
    const float* w_in  = (const float*)d_in[1];
    const float* w0    = (const float*)d_in[2];
    const float* bnp0  = (const float*)d_in[3];
    const float* w0a   = (const float*)d_in[4];
    const float* bnp0a = (const float*)d_in[5];
    const float* w0b   = (const float*)d_in[6];
    const float* bnp0b = (const float*)d_in[7];
    const float* w1    = (const float*)d_in[8];
    const float* bnp1  = (const float*)d_in[9];
    const float* w1a   = (const float*)d_in[10];
    const float* bnp1a = (const float*)d_in[11];
    const float* w1b   = (const float*)d_in[12];
    const float* bnp1b = (const float*)d_in[13];
    const float* ct0_w = (const float*)d_in[14];
    const float* ct0_b = (const float*)d_in[15];
    const float* bnt0  = (const float*)d_in[16];
    const float* ct1_w = (const float*)d_in[17];
    const float* ct1_b = (const float*)d_in[18];
    const float* bnt1  = (const float*)d_in[19];
    const int* coords0 = (const int*)d_in[20];
    const int* coords1 = (const int*)d_in[21];
    const int* g0      = (const int*)d_in[22];
    const int* s0      = (const int*)d_in[23];
    const int* ga      = (const int*)d_in[24];
    const int* sa      = (const int*)d_in[25];
    const int* g1      = (const int*)d_in[26];
    const int* s1      = (const int*)d_in[27];
    const int* gb      = (const int*)d_in[28];
    const int* sb      = (const int*)d_in[29];
    float* out = (float*)d_out;

    float *fin, *f0a, *f0b, *f1a, *f1b, *d0, *d1, *w0p, *w1p;
    int* cnt;
    cudaGetSymbolAddress((void**)&fin,  g_fin);
    cudaGetSymbolAddress((void**)&f0a,  g_f0a);
    cudaGetSymbolAddress((void**)&f0b,  g_f0b);
    cudaGetSymbolAddress((void**)&f1a,  g_f1a);
    cudaGetSymbolAddress((void**)&f1b,  g_f1b);
    cudaGetSymbolAddress((void**)&d0,   g_d0);
    cudaGetSymbolAddress((void**)&d1,   g_d1);
    cudaGetSymbolAddress((void**)&w0p,  g_w0p);
    cudaGetSymbolAddress((void**)&w1p,  g_w1p);
    cudaGetSymbolAddress((void**)&cnt,  g_cnt);

    static cudaStream_t s1s = nullptr;
    static cudaEvent_t evFork = nullptr, evF0a = nullptr, evBev0 = nullptr,
                       evSide = nullptr;
    if (s1s == nullptr) {
        cudaStreamCreateWithFlags(&s1s, cudaStreamNonBlocking);
        cudaEventCreateWithFlags(&evFork, cudaEventDisableTiming);
        cudaEventCreateWithFlags(&evF0a, cudaEventDisableTiming);
        cudaEventCreateWithFlags(&evBev0, cudaEventDisableTiming);
        cudaEventCreateWithFlags(&evSide, cudaEventDisableTiming);
    }

    const int BS = 256;

    // fork: side stream does input-only work (d0/d1 memsets + both weight permutes)
    cudaEventRecord(evFork, 0);
    cudaStreamWaitEvent(s1s, evFork, 0);
    cudaMemsetAsync(d0, 0, (size_t)2 * HW * 320 * sizeof(float), s1s);
    cudaMemsetAsync(d1, 0, (size_t)2 * HW1 * 320 * sizeof(float), s1s);
    k_permw0<<<blocks_for(320 * 64, BS), BS, 0, s1s>>>(ct0_w, w0p);
    k_permw1<<<blocks_for(320 * 256, BS), BS, 0, s1s>>>(ct1_w, w1p);
    cudaEventRecord(evSide, s1s);

    // main stream: counts, input GEMM, stage 0
    k_counts<<<1, 128>>>(s0, sa, s1, sb);
    k_gemm_in<<<blocks_for((long long)NIN * 32, BS), BS>>>(sp, w_in, fin);

    cudaMemsetAsync(f0a, 0, (size_t)(CAP0 + 1) * 32 * sizeof(float), 0);
    k_spconv32<false, 48><<<27 * 48, 128>>>(fin, g0, s0, w0, nullptr, f0a, NIN, cnt);

    cudaMemsetAsync(f0b, 0, (size_t)(CAP0 + 1) * 32 * sizeof(float), 0);
    k_spconv32<true, 96><<<27 * 96, 128>>>(f0a, ga, sa, w0a, bnp0, f0b, CAP0, cnt + 27);

    cudaMemsetAsync(f0a, 0, (size_t)(CAP0 + 1) * 32 * sizeof(float), 0);
    k_spconv32<true, 96><<<27 * 96, 128>>>(f0b, ga, sa, w0b, bnp0a, f0a, CAP0, cnt + 27);

    // f0a ready: fork dense BEV0 path (scatter -> fused GEMM+fusion) onto side stream
    cudaEventRecord(evF0a, 0);
    cudaStreamWaitEvent(s1s, evF0a, 0);
    k_scatter0<<<1184, 256, 0, s1s>>>(f0a, coords0, bnp0b, d0);
    k_gemm_bev0f<<<HW / 32, 256, 0, s1s>>>(d0, w0p, ct0_b, bnt0, out);
    cudaEventRecord(evBev0, s1s);

    // main stream: stage 1 spconvs concurrent with BEV0 dense path
    cudaMemsetAsync(f1a, 0, (size_t)(CAP1 + 1) * 64 * sizeof(float), 0);
    k_spconv3264<true, 96><<<27 * 96, 128>>>(f0a, g1, s1, w1, bnp0b, f1a, CAP0, cnt + 54);

    cudaMemsetAsync(f1b, 0, (size_t)(CAP1 + 1) * 64 * sizeof(float), 0);
    k_spconv64<true, 192><<<27 * 192, 64>>>(f1a, gb, sb, w1a, bnp1, f1b, CAP1, cnt + 81);

    cudaMemsetAsync(f1a, 0, (size_t)(CAP1 + 1) * 64 * sizeof(float), 0);
    k_spconv64<true, 192><<<27 * 192, 64>>>(f1b, gb, sb, w1b, bnp1a, f1a, CAP1, cnt + 81);

    // dense BEV1 on main (d1 + w1p prepared on side stream at fork)
    cudaStreamWaitEvent(0, evSide, 0);
    k_scatter1<<<592, 256>>>(f1a, coords1, bnp1b, d1);
    cudaStreamWaitEvent(0, evBev0, 0);   // join side stream before final kernel
    {
        dim3 grid(HW1 / 32, 4);
        k_gemm_bev1f<<<grid, 256>>>(d1, w1p, ct1_b, bnt1, out);
    }
}

// round 16
// speedup vs baseline: 1.3689x; 1.1242x over previous
#include <cuda_runtime.h>
#include <math.h>

// ---------------- problem constants ----------------
#define NIN    20000          // B_AG * N_PTS
#define CAP0   540000         // 27 * NIN
#define CAP1   352000         // B_AG * Z1*Y1*X1
#define ZD     10
#define YD     200
#define XD     704
#define Z1D    5
#define Y1D    100
#define X1D    352
#define HW     (YD*XD)        // 140800
#define HW1    (Y1D*X1D)      // 35200
#define EPSB   1e-5f

// ---------------- static device scratch ----------------
__device__ float g_fin [NIN * 32];
__device__ float g_f0a [(CAP0 + 1) * 32];
__device__ float g_f0b [(CAP0 + 1) * 32];
__device__ float g_f1a [(CAP1 + 1) * 64];
__device__ float g_f1b [(CAP1 + 1) * 64];
__device__ float g_d0  [2 * HW  * 320];              // [b*HW+p][z*32+c]
__device__ float g_d1  [2 * HW1 * 320];              // [b*HW1+p][z*64+c]
__device__ float g_w0p [320 * 64];
__device__ float g_w1p [320 * 256];
__device__ int   g_cnt [108];

// ---------------- packed f32x2 helpers ----------------
__device__ __forceinline__ void fma2(unsigned long long& acc, unsigned long long a,
                                     unsigned long long b) {
    asm("fma.rn.f32x2 %0, %1, %2, %0;" : "+l"(acc) : "l"(a), "l"(b));
}
__device__ __forceinline__ void lds_2x64(unsigned long long& a, unsigned long long& b,
                                         unsigned addr) {
    asm volatile("ld.shared.v2.b64 {%0, %1}, [%2];" : "=l"(a), "=l"(b) : "r"(addr));
}
__device__ __forceinline__ unsigned long long pack2(float x, float y) {
    unsigned long long r;
    asm("mov.b64 %0, {%1, %2};" : "=l"(r) : "f"(x), "f"(y));
    return r;
}
__device__ __forceinline__ float hsum2(unsigned long long a) {
    float x, y;
    asm("mov.b64 {%0, %1}, %2;" : "=f"(x), "=f"(y) : "l"(a));
    return x + y;
}
__device__ __forceinline__ void redv2(float* p, float a, float b) {
    asm volatile("red.global.add.v2.f32 [%0], {%1, %2};" :: "l"(p), "f"(a), "f"(b)
                 : "memory");
}

// ---------------- rulebook pair counts ----------------
__global__ void k_counts(const int* __restrict__ s0, const int* __restrict__ sa,
                         const int* __restrict__ s1, const int* __restrict__ sb) {
    int t = blockIdx.x * blockDim.x + threadIdx.x;
    if (t >= 108) return;
    int rb = t / 27, k = t % 27;
    const int* S; int pc, cap;
    if      (rb == 0) { S = s0; pc = NIN;  cap = CAP0; }
    else if (rb == 1) { S = sa; pc = CAP0; cap = CAP0; }
    else if (rb == 2) { S = s1; pc = CAP0; cap = CAP1; }
    else              { S = sb; pc = CAP1; cap = CAP1; }
    const int* row = S + (size_t)k * pc;
    int lo = 0, hi = pc;
    while (lo < hi) {
        int mid = (lo + hi) >> 1;
        if (row[mid] == cap) hi = mid; else lo = mid + 1;
    }
    g_cnt[t] = lo;
}

// ---------------- input GEMM ----------------
__global__ void k_gemm_in(const float* __restrict__ sp, const float* __restrict__ w,
                          float* __restrict__ out) {
    int t = blockIdx.x * blockDim.x + threadIdx.x;
    if (t >= NIN * 32) return;
    int i = t >> 5, j = t & 31;
    const float* r = sp + i * 64;
    float acc = 0.f;
#pragma unroll
    for (int c = 0; c < 64; c++) acc += r[c] * w[c * 32 + j];
    out[t] = acc;
}

// ---------------- spconv CIN=32 COUT=32: 128-thread blocks, 2 pairs/warp -------------
template<bool BN, int NB>
__global__ void __launch_bounds__(128) k_spconv32(
    const float* __restrict__ feats, const int* __restrict__ G, const int* __restrict__ S,
    const float* __restrict__ W, const float* __restrict__ bn,
    float* __restrict__ out, int pair_cap, const int* __restrict__ cnt) {
    __shared__ float slot[4][2][2][32];
    int k = blockIdx.x / NB;
    int lane = threadIdx.x & 31;
    int warp = threadIdx.x >> 5;             // 0..3
    int half = lane >> 4;
    int j = lane & 15;
    const float* Wk = W + (size_t)k * 1024;
    unsigned long long wA[16], wB[16];
#pragma unroll
    for (int i = 0; i < 16; i++) {
        wA[i] = pack2(Wk[(2 * i) * 32 + 2 * j],     Wk[(2 * i + 1) * 32 + 2 * j]);
        wB[i] = pack2(Wk[(2 * i) * 32 + 2 * j + 1], Wk[(2 * i + 1) * 32 + 2 * j + 1]);
    }
    float sc[4] = {1.f,1.f,1.f,1.f}, of[4] = {0.f,0.f,0.f,0.f};
    if (BN && j < 8) {
#pragma unroll
        for (int c = 0; c < 4; c++) {
            int idx = 4 * j + c;
            sc[c] = bn[idx] * rsqrtf(bn[96 + idx] + EPSB);
            of[c] = bn[32 + idx] - bn[64 + idx] * sc[c];
        }
    }
    int n = cnt[k];
    const int* Gk = G + (size_t)k * pair_cap;
    const int* Sk = S + (size_t)k * pair_cap;
    int base = ((blockIdx.x % NB) * 4 + warp) * 2;
    const int stride = NB * 8;
    unsigned sa0 = (unsigned)__cvta_generic_to_shared(&slot[warp][0][half][0]);
    unsigned sa1 = (unsigned)__cvta_generic_to_shared(&slot[warp][1][half][0]);
    for (int pb = base; pb < n; pb += 2 * stride) {
        int p0 = pb + half, p1 = pb + stride + half;
        bool a0 = p0 < n, a1 = p1 < n;
        int g0 = 0, s0 = 0, g1 = 0, s1 = 0;
        if (a0) { g0 = Gk[p0]; s0 = Sk[p0]; }
        if (a1) { g1 = Gk[p1]; s1 = Sk[p1]; }
        float4 f0 = make_float4(0,0,0,0), f1 = make_float4(0,0,0,0);
        if (a0 && j < 8) f0 = *(const float4*)(feats + (size_t)g0 * 32 + 4 * j);
        if (a1 && j < 8) f1 = *(const float4*)(feats + (size_t)g1 * 32 + 4 * j);
        if (j < 8) {
            if (BN) {
                f0.x = fmaxf(f0.x * sc[0] + of[0], 0.f); f0.y = fmaxf(f0.y * sc[1] + of[1], 0.f);
                f0.z = fmaxf(f0.z * sc[2] + of[2], 0.f); f0.w = fmaxf(f0.w * sc[3] + of[3], 0.f);
                f1.x = fmaxf(f1.x * sc[0] + of[0], 0.f); f1.y = fmaxf(f1.y * sc[1] + of[1], 0.f);
                f1.z = fmaxf(f1.z * sc[2] + of[2], 0.f); f1.w = fmaxf(f1.w * sc[3] + of[3], 0.f);
            }
            if (a0) *(float4*)&slot[warp][0][half][4 * j] = f0;
            if (a1) *(float4*)&slot[warp][1][half][4 * j] = f1;
        }
        __syncwarp();
        unsigned long long A = 0ull, B = 0ull;
#pragma unroll
        for (int i = 0; i < 8; i++) {
            unsigned long long va, vb;
            lds_2x64(va, vb, sa0 + i * 16);
            fma2(A, va, wA[2 * i]); fma2(B, va, wB[2 * i]);
            fma2(A, vb, wA[2 * i + 1]); fma2(B, vb, wB[2 * i + 1]);
        }
        if (a0) redv2(out + (size_t)s0 * 32 + 2 * j, hsum2(A), hsum2(B));
        A = 0ull; B = 0ull;
#pragma unroll
        for (int i = 0; i < 8; i++) {
            unsigned long long va, vb;
            lds_2x64(va, vb, sa1 + i * 16);
            fma2(A, va, wA[2 * i]); fma2(B, va, wB[2 * i]);
            fma2(A, vb, wA[2 * i + 1]); fma2(B, vb, wB[2 * i + 1]);
        }
        if (a1) redv2(out + (size_t)s1 * 32 + 2 * j, hsum2(A), hsum2(B));
        __syncwarp();
    }
}

// ---------------- spconv CIN=32 COUT=64: 128-thread blocks, warp/pair ----------------
template<bool BN, int NB>
__global__ void __launch_bounds__(128) k_spconv3264(
    const float* __restrict__ feats, const int* __restrict__ G, const int* __restrict__ S,
    const float* __restrict__ W, const float* __restrict__ bn,
    float* __restrict__ out, int pair_cap, const int* __restrict__ cnt) {
    __shared__ float slot[4][2][32];
    int k = blockIdx.x / NB;
    int lane = threadIdx.x & 31;
    int warp = threadIdx.x >> 5;             // 0..3
    const float* Wk = W + (size_t)k * 2048;
    unsigned long long wA[16], wB[16];
#pragma unroll
    for (int i = 0; i < 16; i++) {
        wA[i] = pack2(Wk[(2 * i) * 64 + 2 * lane],     Wk[(2 * i + 1) * 64 + 2 * lane]);
        wB[i] = pack2(Wk[(2 * i) * 64 + 2 * lane + 1], Wk[(2 * i + 1) * 64 + 2 * lane + 1]);
    }
    float sc[4] = {1.f,1.f,1.f,1.f}, of[4] = {0.f,0.f,0.f,0.f};
    if (BN && lane < 8) {
#pragma unroll
        for (int c = 0; c < 4; c++) {
            int idx = 4 * lane + c;
            sc[c] = bn[idx] * rsqrtf(bn[96 + idx] + EPSB);
            of[c] = bn[32 + idx] - bn[64 + idx] * sc[c];
        }
    }
    int n = cnt[k];
    const int* Gk = G + (size_t)k * pair_cap;
    const int* Sk = S + (size_t)k * pair_cap;
    int base = (blockIdx.x % NB) * 4 + warp;
    const int stride = NB * 4;
    unsigned sa0 = (unsigned)__cvta_generic_to_shared(&slot[warp][0][0]);
    unsigned sa1 = (unsigned)__cvta_generic_to_shared(&slot[warp][1][0]);
    for (int p = base; p < n; p += 2 * stride) {
        int p1 = p + stride;
        bool a1 = p1 < n;
        int g0 = Gk[p], s0 = Sk[p], g1 = 0, s1 = 0;
        if (a1) { g1 = Gk[p1]; s1 = Sk[p1]; }
        float4 f0 = make_float4(0,0,0,0), f1 = make_float4(0,0,0,0);
        if (lane < 8) {
            f0 = *(const float4*)(feats + (size_t)g0 * 32 + 4 * lane);
            if (a1) f1 = *(const float4*)(feats + (size_t)g1 * 32 + 4 * lane);
            if (BN) {
                f0.x = fmaxf(f0.x * sc[0] + of[0], 0.f); f0.y = fmaxf(f0.y * sc[1] + of[1], 0.f);
                f0.z = fmaxf(f0.z * sc[2] + of[2], 0.f); f0.w = fmaxf(f0.w * sc[3] + of[3], 0.f);
                f1.x = fmaxf(f1.x * sc[0] + of[0], 0.f); f1.y = fmaxf(f1.y * sc[1] + of[1], 0.f);
                f1.z = fmaxf(f1.z * sc[2] + of[2], 0.f); f1.w = fmaxf(f1.w * sc[3] + of[3], 0.f);
            }
            *(float4*)&slot[warp][0][4 * lane] = f0;
            if (a1) *(float4*)&slot[warp][1][4 * lane] = f1;
        }
        __syncwarp();
        unsigned long long A = 0ull, B = 0ull;
#pragma unroll
        for (int i = 0; i < 8; i++) {
            unsigned long long va, vb;
            lds_2x64(va, vb, sa0 + i * 16);
            fma2(A, va, wA[2 * i]); fma2(B, va, wB[2 * i]);
            fma2(A, vb, wA[2 * i + 1]); fma2(B, vb, wB[2 * i + 1]);
        }
        redv2(out + (size_t)s0 * 64 + 2 * lane, hsum2(A), hsum2(B));
        if (a1) {
            A = 0ull; B = 0ull;
#pragma unroll
            for (int i = 0; i < 8; i++) {
                unsigned long long va, vb;
                lds_2x64(va, vb, sa1 + i * 16);
                fma2(A, va, wA[2 * i]); fma2(B, va, wB[2 * i]);
                fma2(A, vb, wA[2 * i + 1]); fma2(B, vb, wB[2 * i + 1]);
            }
            redv2(out + (size_t)s1 * 64 + 2 * lane, hsum2(A), hsum2(B));
        }
        __syncwarp();
    }
}

// ---------------- spconv CIN=64 COUT=64: 64-thread blocks, warp/pair, BATCH-4 --------
template<bool BN, int NB>
__global__ void __launch_bounds__(64) k_spconv64(
    const float* __restrict__ feats, const int* __restrict__ G, const int* __restrict__ S,
    const float* __restrict__ W, const float* __restrict__ bn,
    float* __restrict__ out, int pair_cap, const int* __restrict__ cnt) {
    __shared__ float slot[2][4][64];         // [warp][buf][feature row]
    int k = blockIdx.x / NB;
    int lane = threadIdx.x & 31;
    int warp = threadIdx.x >> 5;             // 0..1
    const float* Wk = W + (size_t)k * 4096;
    unsigned long long wA[32], wB[32];
#pragma unroll
    for (int i = 0; i < 32; i++) {
        wA[i] = pack2(Wk[(2 * i) * 64 + 2 * lane],     Wk[(2 * i + 1) * 64 + 2 * lane]);
        wB[i] = pack2(Wk[(2 * i) * 64 + 2 * lane + 1], Wk[(2 * i + 1) * 64 + 2 * lane + 1]);
    }
    float sc0 = 1.f, of0 = 0.f, sc1 = 1.f, of1 = 0.f;
    if (BN) {
        int c0 = 2 * lane, c1 = 2 * lane + 1;
        sc0 = bn[c0] * rsqrtf(bn[192 + c0] + EPSB);
        of0 = bn[64 + c0] - bn[128 + c0] * sc0;
        sc1 = bn[c1] * rsqrtf(bn[192 + c1] + EPSB);
        of1 = bn[64 + c1] - bn[128 + c1] * sc1;
    }
    int n = cnt[k];
    const int* Gk = G + (size_t)k * pair_cap;
    const int* Sk = S + (size_t)k * pair_cap;
    int base = (blockIdx.x % NB) * 2 + warp;
    const int stride = NB * 2;
    unsigned sbase = (unsigned)__cvta_generic_to_shared(&slot[warp][0][0]);
    for (int p = base; p < n; p += 4 * stride) {
        int pp[4] = {p, p + stride, p + 2 * stride, p + 3 * stride};
        bool act[4];
        int ss[4];
        float2 fv[4];
#pragma unroll
        for (int q = 0; q < 4; q++) {
            act[q] = pp[q] < n;
            ss[q] = 0;
            fv[q] = make_float2(0.f, 0.f);
            if (act[q]) {
                int g = Gk[pp[q]];
                ss[q] = Sk[pp[q]];
                fv[q] = *(const float2*)(feats + (size_t)g * 64 + 2 * lane);
            }
        }
#pragma unroll
        for (int q = 0; q < 4; q++) {
            if (BN) {
                fv[q].x = fmaxf(fv[q].x * sc0 + of0, 0.f);
                fv[q].y = fmaxf(fv[q].y * sc1 + of1, 0.f);
            }
            if (act[q]) *(float2*)&slot[warp][q][2 * lane] = fv[q];
        }
        __syncwarp();
#pragma unroll
        for (int q = 0; q < 4; q++) {
            if (!act[q]) break;
            unsigned long long A = 0ull, B = 0ull;
            unsigned sa = sbase + q * 256;
#pragma unroll
            for (int i = 0; i < 16; i++) {
                unsigned long long va, vb;
                lds_2x64(va, vb, sa + i * 16);
                fma2(A, va, wA[2 * i]); fma2(B, va, wB[2 * i]);
                fma2(A, vb, wA[2 * i + 1]); fma2(B, vb, wB[2 * i + 1]);
            }
            redv2(out + (size_t)ss[q] * 64 + 2 * lane, hsum2(A), hsum2(B));
        }
        __syncwarp();
    }
}

// ---------------- sparse -> dense scatter with fused BN+ReLU ----------------
__global__ void k_scatter0(const float* __restrict__ f, const int* __restrict__ co,
                           const float* __restrict__ bn, float* __restrict__ d0) {
    int lane = threadIdx.x & 31;
    float sc = bn[lane] * rsqrtf(bn[96 + lane] + EPSB);
    float of = bn[32 + lane] - bn[64 + lane] * sc;
    int warps_total = (gridDim.x * blockDim.x) >> 5;
    for (unsigned w = (blockIdx.x * blockDim.x + threadIdx.x) >> 5; w < CAP0;
         w += warps_total) {
        int z = co[4 * w + 1];
        if ((unsigned)z >= (unsigned)ZD) continue;
        int b = co[4 * w], y = co[4 * w + 2], x = co[4 * w + 3];
        size_t base = ((size_t)(b * HW + y * XD + x)) * 320 + z * 32;
        d0[base + lane] = fmaxf(f[(size_t)w * 32 + lane] * sc + of, 0.f);
    }
}

__global__ void k_scatter1(const float* __restrict__ f, const int* __restrict__ co,
                           const float* __restrict__ bn, float* __restrict__ d1) {
    int lane = threadIdx.x & 31;
    float scA = bn[lane] * rsqrtf(bn[192 + lane] + EPSB);
    float ofA = bn[64 + lane] - bn[128 + lane] * scA;
    float scB = bn[lane + 32] * rsqrtf(bn[192 + lane + 32] + EPSB);
    float ofB = bn[64 + lane + 32] - bn[128 + lane + 32] * scB;
    int warps_total = (gridDim.x * blockDim.x) >> 5;
    for (unsigned w = (blockIdx.x * blockDim.x + threadIdx.x) >> 5; w < CAP1;
         w += warps_total) {
        int z = co[4 * w + 1];
        if ((unsigned)z >= (unsigned)Z1D) continue;
        int b = co[4 * w], y = co[4 * w + 2], x = co[4 * w + 3];
        size_t base = ((size_t)(b * HW1 + y * X1D + x)) * 320 + z * 64;
        d1[base + lane]      = fmaxf(f[(size_t)w * 64 + lane] * scA + ofA, 0.f);
        d1[base + lane + 32] = fmaxf(f[(size_t)w * 64 + lane + 32] * scB + ofB, 0.f);
    }
}

// ---------------- weight permutes ----------------
__global__ void k_permw0(const float* __restrict__ w, float* __restrict__ wp) {
    int t = blockIdx.x * blockDim.x + threadIdx.x;
    if (t >= 320 * 64) return;
    int o = t & 63, kk = t >> 6;
    int z = kk >> 5, c = kk & 31;
    wp[t] = w[(c * 10 + z) * 64 + o];
}
__global__ void k_permw1(const float* __restrict__ w, float* __restrict__ wp) {
    int t = blockIdx.x * blockDim.x + threadIdx.x;
    if (t >= 320 * 256) return;
    int col = t & 255, kk = t >> 8;
    int ij = col >> 6, o = col & 63;
    int z = kk >> 6, c = kk & 63;
    wp[t] = w[((c * 5 + z) * 64 + o) * 4 + ij];
}

// ---------------- GEMM + BN + ReLU + 2-agent attention fusion, BEV0 ------------------
__global__ void k_gemm_bev0f(const float* __restrict__ A, const float* __restrict__ B,
                             const float* __restrict__ bias, const float* __restrict__ bn,
                             float* __restrict__ out) {
    __shared__ float As[16][72];
    __shared__ float Bs[16][64];
    __shared__ float Cs[64][65];
    __shared__ float w0s[32], w1s[32];
    int tid = threadIdx.x;
    int tx = tid & 15, ty = tid >> 4;
    int px0 = blockIdx.x * 32;
    float acc[4][4] = {};
    int lr = tid >> 2, lk = (tid & 3) * 4;
    int bk = tid >> 4, bc = (tid & 15) * 4;
    size_t arow = (lr < 32) ? (size_t)(px0 + lr) : (size_t)HW + px0 + (lr - 32);
    for (int k0 = 0; k0 < 320; k0 += 16) {
        float4 av = *(const float4*)(A + arow * 320 + k0 + lk);
        As[lk + 0][lr] = av.x; As[lk + 1][lr] = av.y;
        As[lk + 2][lr] = av.z; As[lk + 3][lr] = av.w;
        *(float4*)&Bs[bk][bc] = *(const float4*)(B + (size_t)(k0 + bk) * 64 + bc);
        __syncthreads();
#pragma unroll
        for (int kk = 0; kk < 16; kk++) {
            float4 a4 = *(const float4*)&As[kk][ty * 4];
            float4 b4 = *(const float4*)&Bs[kk][tx * 4];
            float aa[4] = {a4.x, a4.y, a4.z, a4.w};
            float bb[4] = {b4.x, b4.y, b4.z, b4.w};
#pragma unroll
            for (int i = 0; i < 4; i++)
#pragma unroll
                for (int j = 0; j < 4; j++) acc[i][j] += aa[i] * bb[j];
        }
        __syncthreads();
    }
#pragma unroll
    for (int j = 0; j < 4; j++) {
        int o = tx * 4 + j;
        float sc = bn[o] * rsqrtf(bn[192 + o] + EPSB);
        float ofs = bn[64 + o] + (bias[o] - bn[128 + o]) * sc;
#pragma unroll
        for (int i = 0; i < 4; i++)
            Cs[ty * 4 + i][o] = fmaxf(acc[i][j] * sc + ofs, 0.f);
    }
    __syncthreads();
    {
        int q = tid >> 3, sub = tid & 7;
        float l00 = 0.f, l01 = 0.f;
#pragma unroll
        for (int c = sub * 8; c < sub * 8 + 8; c++) {
            float x0 = Cs[q][c], x1 = Cs[32 + q][c];
            l00 += x0 * x0; l01 += x0 * x1;
        }
#pragma unroll
        for (int m = 4; m; m >>= 1) {
            l00 += __shfl_xor_sync(0xffffffffu, l00, m);
            l01 += __shfl_xor_sync(0xffffffffu, l01, m);
        }
        if (sub == 0) {
            l00 *= 0.125f; l01 *= 0.125f;
            float mm = fmaxf(l00, l01);
            float e0 = expf(l00 - mm), e1 = expf(l01 - mm);
            float inv = 1.f / (e0 + e1);
            w0s[q] = e0 * inv; w1s[q] = e1 * inv;
        }
    }
    __syncthreads();
    {
        int q = tid & 31, cb = tid >> 5;
        float a0 = w0s[q], a1 = w1s[q];
#pragma unroll
        for (int it = 0; it < 8; it++) {
            int c = cb * 8 + it;
            out[(size_t)c * HW + px0 + q] = a0 * Cs[q][c] + a1 * Cs[32 + q][c];
        }
    }
}

// ---------------- GEMM(convT) + BN + ReLU + fusion, BEV1 -----------------------------
__global__ void k_gemm_bev1f(const float* __restrict__ A, const float* __restrict__ B,
                             const float* __restrict__ bias, const float* __restrict__ bn,
                             float* __restrict__ out) {
    __shared__ float As[16][72];
    __shared__ float Bs[16][64];
    __shared__ float Cs[64][65];
    __shared__ float w0s[32], w1s[32];
    int tid = threadIdx.x;
    int tx = tid & 15, ty = tid >> 4;
    int px0 = blockIdx.x * 32;
    int colbase = blockIdx.y * 64;
    float acc[4][4] = {};
    int lr = tid >> 2, lk = (tid & 3) * 4;
    int bk = tid >> 4, bc = (tid & 15) * 4;
    size_t arow = (lr < 32) ? (size_t)(px0 + lr) : (size_t)HW1 + px0 + (lr - 32);
    for (int k0 = 0; k0 < 320; k0 += 16) {
        float4 av = *(const float4*)(A + arow * 320 + k0 + lk);
        As[lk + 0][lr] = av.x; As[lk + 1][lr] = av.y;
        As[lk + 2][lr] = av.z; As[lk + 3][lr] = av.w;
        *(float4*)&Bs[bk][bc] = *(const float4*)(B + (size_t)(k0 + bk) * 256 + colbase + bc);
        __syncthreads();
#pragma unroll
        for (int kk = 0; kk < 16; kk++) {
            float4 a4 = *(const float4*)&As[kk][ty * 4];
            float4 b4 = *(const float4*)&Bs[kk][tx * 4];
            float aa[4] = {a4.x, a4.y, a4.z, a4.w};
            float bb[4] = {b4.x, b4.y, b4.z, b4.w};
#pragma unroll
            for (int i = 0; i < 4; i++)
#pragma unroll
                for (int j = 0; j < 4; j++) acc[i][j] += aa[i] * bb[j];
        }
        __syncthreads();
    }
#pragma unroll
    for (int j = 0; j < 4; j++) {
        int o = tx * 4 + j;
        float sc = bn[o] * rsqrtf(bn[192 + o] + EPSB);
        float ofs = bn[64 + o] + (bias[o] - bn[128 + o]) * sc;
#pragma unroll
        for (int i = 0; i < 4; i++)
            Cs[ty * 4 + i][o] = fmaxf(acc[i][j] * sc + ofs, 0.f);
    }
    __syncthreads();
    {
        int q = tid >> 3, sub = tid & 7;
        float l00 = 0.f, l01 = 0.f;
#pragma unroll
        for (int c = sub * 8; c < sub * 8 + 8; c++) {
            float x0 = Cs[q][c], x1 = Cs[32 + q][c];
            l00 += x0 * x0; l01 += x0 * x1;
        }
#pragma unroll
        for (int m = 4; m; m >>= 1) {
            l00 += __shfl_xor_sync(0xffffffffu, l00, m);
            l01 += __shfl_xor_sync(0xffffffffu, l01, m);
        }
        if (sub == 0) {
            l00 *= 0.125f; l01 *= 0.125f;
            float mm = fmaxf(l00, l01);
            float e0 = expf(l00 - mm), e1 = expf(l01 - mm);
            float inv = 1.f / (e0 + e1);
            w0s[q] = e0 * inv; w1s[q] = e1 * inv;
        }
    }
    __syncthreads();
    {
        int ij = blockIdx.y, ii = ij >> 1, jj = ij & 1;
        int q = tid & 31, cb = tid >> 5;
        int ip = px0 + q;
        int y = ip / X1D, x = ip - y * X1D;
        size_t opix = (size_t)(2 * y + ii) * XD + 2 * x + jj;
        float a0 = w0s[q], a1 = w1s[q];
#pragma unroll
        for (int it = 0; it < 8; it++) {
            int c = cb * 8 + it;
            out[(size_t)(64 + c) * HW + opix] = a0 * Cs[q][c] + a1 * Cs[32 + q][c];
        }
    }
}

// ---------------- host launcher ----------------
static inline unsigned blocks_for(long long threads, int bs) {
    return (unsigned)((threads + bs - 1) / bs);
}

extern "C" void kernel_launch(void* const* d_in, const int* in_sizes, int n_in,
                              void* d_out, int out_size) {
    const float* sp    = (const float*)d_in[0];
    const float* w_in  = (const float*)d_in[1];
    const float* w0    = (const float*)d_in[2];
    const float* bnp0  = (const float*)d_in[3];
    const float* w0a   = (const float*)d_in[4];
    const float* bnp0a = (const float*)d_in[5];
    const float* w0b   = (const float*)d_in[6];
    const float* bnp0b = (const float*)d_in[7];
    const float* w1    = (const float*)d_in[8];
    const float* bnp1  = (const float*)d_in[9];
    const float* w1a   = (const float*)d_in[10];
    const float* bnp1a = (const float*)d_in[11];
    const float* w1b   = (const float*)d_in[12];
    const float* bnp1b = (const float*)d_in[13];
    const float* ct0_w = (const float*)d_in[14];
    const float* ct0_b = (const float*)d_in[15];
    const float* bnt0  = (const float*)d_in[16];
    const float* ct1_w = (const float*)d_in[17];
    const float* ct1_b = (const float*)d_in[18];
    const float* bnt1  = (const float*)d_in[19];
    const int* coords0 = (const int*)d_in[20];
    const int* coords1 = (const int*)d_in[21];
    const int* g0      = (const int*)d_in[22];
    const int* s0      = (const int*)d_in[23];
    const int* ga      = (const int*)d_in[24];
    const int* sa      = (const int*)d_in[25];
    const int* g1      = (const int*)d_in[26];
    const int* s1      = (const int*)d_in[27];
    const int* gb      = (const int*)d_in[28];
    const int* sb      = (const int*)d_in[29];
    float* out = (float*)d_out;

    float *fin, *f0a, *f0b, *f1a, *f1b, *d0, *d1, *w0p, *w1p;
    int* cnt;
    cudaGetSymbolAddress((void**)&fin,  g_fin);
    cudaGetSymbolAddress((void**)&f0a,  g_f0a);
    cudaGetSymbolAddress((void**)&f0b,  g_f0b);
    cudaGetSymbolAddress((void**)&f1a,  g_f1a);
    cudaGetSymbolAddress((void**)&f1b,  g_f1b);
    cudaGetSymbolAddress((void**)&d0,   g_d0);
    cudaGetSymbolAddress((void**)&d1,   g_d1);
    cudaGetSymbolAddress((void**)&w0p,  g_w0p);
    cudaGetSymbolAddress((void**)&w1p,  g_w1p);
    cudaGetSymbolAddress((void**)&cnt,  g_cnt);

    static cudaStream_t s1s = nullptr;
    static cudaEvent_t evFork = nullptr, evF0a = nullptr, evBev0 = nullptr,
                       evSide = nullptr;
    if (s1s == nullptr) {
        cudaStreamCreateWithFlags(&s1s, cudaStreamNonBlocking);
        cudaEventCreateWithFlags(&evFork, cudaEventDisableTiming);
        cudaEventCreateWithFlags(&evF0a, cudaEventDisableTiming);
        cudaEventCreateWithFlags(&evBev0, cudaEventDisableTiming);
        cudaEventCreateWithFlags(&evSide, cudaEventDisableTiming);
    }

    const int BS = 256;

    // fork: side stream does input-only work (d0/d1 memsets + both weight permutes)
    cudaEventRecord(evFork, 0);
    cudaStreamWaitEvent(s1s, evFork, 0);
    cudaMemsetAsync(d0, 0, (size_t)2 * HW * 320 * sizeof(float), s1s);
    cudaMemsetAsync(d1, 0, (size_t)2 * HW1 * 320 * sizeof(float), s1s);
    k_permw0<<<blocks_for(320 * 64, BS), BS, 0, s1s>>>(ct0_w, w0p);
    k_permw1<<<blocks_for(320 * 256, BS), BS, 0, s1s>>>(ct1_w, w1p);
    cudaEventRecord(evSide, s1s);

    // main stream: counts, input GEMM, stage 0
    k_counts<<<1, 128>>>(s0, sa, s1, sb);
    k_gemm_in<<<blocks_for((long long)NIN * 32, BS), BS>>>(sp, w_in, fin);

    cudaMemsetAsync(f0a, 0, (size_t)(CAP0 + 1) * 32 * sizeof(float), 0);
    k_spconv32<false, 48><<<27 * 48, 128>>>(fin, g0, s0, w0, nullptr, f0a, NIN, cnt);

    cudaMemsetAsync(f0b, 0, (size_t)(CAP0 + 1) * 32 * sizeof(float), 0);
    k_spconv32<true, 96><<<27 * 96, 128>>>(f0a, ga, sa, w0a, bnp0, f0b, CAP0, cnt + 27);

    cudaMemsetAsync(f0a, 0, (size_t)(CAP0 + 1) * 32 * sizeof(float), 0);
    k_spconv32<true, 96><<<27 * 96, 128>>>(f0b, ga, sa, w0b, bnp0a, f0a, CAP0, cnt + 27);

    // f0a ready: fork dense BEV0 path (scatter -> fused GEMM+fusion) onto side stream
    cudaEventRecord(evF0a, 0);
    cudaStreamWaitEvent(s1s, evF0a, 0);
    k_scatter0<<<1184, 256, 0, s1s>>>(f0a, coords0, bnp0b, d0);
    k_gemm_bev0f<<<HW / 32, 256, 0, s1s>>>(d0, w0p, ct0_b, bnt0, out);
    cudaEventRecord(evBev0, s1s);

    // main stream: stage 1 spconvs concurrent with BEV0 dense path
    cudaMemsetAsync(f1a, 0, (size_t)(CAP1 + 1) * 64 * sizeof(float), 0);
    k_spconv3264<true, 96><<<27 * 96, 128>>>(f0a, g1, s1, w1, bnp0b, f1a, CAP0, cnt + 54);

    cudaMemsetAsync(f1b, 0, (size_t)(CAP1 + 1) * 64 * sizeof(float), 0);
    k_spconv64<true, 192><<<27 * 192, 64>>>(f1a, gb, sb, w1a, bnp1, f1b, CAP1, cnt + 81);

    cudaMemsetAsync(f1a, 0, (size_t)(CAP1 + 1) * 64 * sizeof(float), 0);
    k_spconv64<true, 192><<<27 * 192, 64>>>(f1b, gb, sb, w1b, bnp1a, f1a, CAP1, cnt + 81);

    // dense BEV1 on main (d1 + w1p prepared on side stream at fork)
    cudaStreamWaitEvent(0, evSide, 0);
    k_scatter1<<<592, 256>>>(f1a, coords1, bnp1b, d1);
    cudaStreamWaitEvent(0, evBev0, 0);   // join side stream before final kernel
    {
        dim3 grid(HW1 / 32, 4);
        k_gemm_bev1f<<<grid, 256>>>(d1, w1p, ct1_b, bnt1, out);
    }
}